// round 11
// baseline (speedup 1.0000x reference)
#include <cuda_runtime.h>
#include <cuda_bf16.h>
#include <cstddef>
#include <cstdint>

#define NU_MAX 100000
#define NI_MAX 100000
#define E_MAX  1000000
#define DIMN   128

// ---------------- scratch (static __device__, no allocation) ----------------
__device__ int   g_cnt[3][NU_MAX + 1];
__device__ int   g_off[3][NU_MAX + 1];
__device__ int   g_cur[3][NU_MAX];
__device__ int   g_adj[3][E_MAX];
__device__ float g_meanB[(size_t)NI_MAX * DIMN];
__device__ float g_meanR[(size_t)NU_MAX * DIMN];
__device__ float g_meanT[(size_t)NI_MAX * DIMN];

// split + transposed weights: [panel][half hi/lo][n*128+k] bf16
__device__ __align__(16) __nv_bfloat16 g_Wsp[5][2][DIMN * DIMN];
__device__ __align__(16) float g_biasU[DIMN];
__device__ __align__(16) float g_biasI[DIMN];

// ---------------- init: zero counters + weight prep (merged) ----------------
__global__ void k_init(const float* __restrict__ WlR, const float* __restrict__ WrR,
                       const float* __restrict__ WlB, const float* __restrict__ WlT,
                       const float* __restrict__ WrB, const float* __restrict__ WrT,
                       const float* __restrict__ bR, const float* __restrict__ bB,
                       const float* __restrict__ bT) {
    int i = blockIdx.x * blockDim.x + threadIdx.x;
    const int total = 3 * (NU_MAX + 1);
    if (i < total) ((int*)g_cnt)[i] = 0;
    if (i < 5 * 16384) {
        int panel = i >> 14;
        int e = i & 16383;
        int k = e >> 7;
        int n = e & 127;
        float v;
        switch (panel) {
            case 0:  v = WlR[k * 128 + n]; break;
            case 1:  v = WrR[k * 128 + n]; break;
            case 2:  v = 0.5f * WlB[k * 128 + n]; break;
            case 3:  v = 0.5f * WlT[k * 128 + n]; break;
            default: v = 0.5f * (WrB[k * 128 + n] + WrT[k * 128 + n]);
        }
        __nv_bfloat16 h = __float2bfloat16_rn(v);
        __nv_bfloat16 l = __float2bfloat16_rn(v - __bfloat162float(h));
        g_Wsp[panel][0][n * 128 + k] = h;
        g_Wsp[panel][1][n * 128 + k] = l;
    }
    if (i < DIMN) {
        g_biasU[i] = bR[i];
        g_biasI[i] = 0.5f * (bB[i] + bT[i]);
    }
}

// ---------------- CSR build (2 edges/thread) ----------------
__global__ void k_hist3(const int* __restrict__ db, const int* __restrict__ dr,
                        const int* __restrict__ dt, int EB, int ER, int ET) {
    int t = blockIdx.x * blockDim.x + threadIdx.x;
    #pragma unroll
    for (int j = 0; j < 2; j++) {
        int e = t * 2 + j;
        if (e < EB) atomicAdd(&g_cnt[0][db[e]], 1);
        else if (e < EB + ER) atomicAdd(&g_cnt[1][dr[e - EB]], 1);
        else if (e < EB + ER + ET) atomicAdd(&g_cnt[2][dt[e - EB - ER]], 1);
    }
}

// warp-shuffle based exclusive scan; 3 blocks (one per relation), 1024 threads
__global__ void k_scan(int n0, int n1, int n2) {
    int rel = blockIdx.x;
    int n = (rel == 0) ? n0 : (rel == 1) ? n1 : n2;
    int lane = threadIdx.x & 31, wid = threadIdx.x >> 5;
    __shared__ int wsum[32];
    __shared__ int carry;
    if (threadIdx.x == 0) carry = 0;
    __syncthreads();
    for (int base = 0; base < n; base += 1024) {
        int i = base + threadIdx.x;
        int v = (i < n) ? g_cnt[rel][i] : 0;
        int s = v;
        #pragma unroll
        for (int d = 1; d < 32; d <<= 1) {
            int t = __shfl_up_sync(0xFFFFFFFFu, s, d);
            if (lane >= d) s += t;
        }
        if (lane == 31) wsum[wid] = s;
        __syncthreads();
        if (wid == 0) {
            int w = wsum[lane];
            #pragma unroll
            for (int d = 1; d < 32; d <<= 1) {
                int t = __shfl_up_sync(0xFFFFFFFFu, w, d);
                if (lane >= d) w += t;
            }
            wsum[lane] = w;
        }
        __syncthreads();
        int woff = (wid > 0) ? wsum[wid - 1] : 0;
        int c = carry;
        int excl = c + woff + s - v;
        if (i < n) { g_off[rel][i] = excl; g_cur[rel][i] = excl; }
        int tot = wsum[31];
        __syncthreads();
        if (threadIdx.x == 0) carry = c + tot;
        __syncthreads();
    }
    if (threadIdx.x == 0) g_off[rel][n] = carry;
}

__global__ void k_fill3(const int* __restrict__ eb, const int* __restrict__ er,
                        const int* __restrict__ et, int EB, int ER, int ET) {
    int t = blockIdx.x * blockDim.x + threadIdx.x;
    #pragma unroll
    for (int j = 0; j < 2; j++) {
        int e = t * 2 + j;
        int rel, idx;
        const int* ei;
        int E;
        if (e < EB) { rel = 0; idx = e; ei = eb; E = EB; }
        else if (e < EB + ER) { rel = 1; idx = e - EB; ei = er; E = ER; }
        else if (e < EB + ER + ET) { rel = 2; idx = e - EB - ER; ei = et; E = ET; }
        else continue;
        int d = ei[E + idx];
        int s = ei[idx];
        int p = atomicAdd(&g_cur[rel][d], 1);
        g_adj[rel][p] = s;
    }
}

// ---------------- mean aggregation: one warp per dst node, unroll-4 (round-9 exact) ----------------
__global__ void k_agg3(const float* __restrict__ xu, const float* __restrict__ xi,
                       const float* __restrict__ xt, int NU, int NI) {
    int w = (blockIdx.x * blockDim.x + threadIdx.x) >> 5;
    int lane = threadIdx.x & 31;
    int rel, node;
    const float* xs;
    float* mean;
    if (w < NI) { rel = 0; node = w; xs = xu; mean = g_meanB; }
    else if (w < NI + NU) { rel = 1; node = w - NI; xs = xi; mean = g_meanR; }
    else if (w < NI + NU + NI) { rel = 2; node = w - NI - NU; xs = xt; mean = g_meanT; }
    else return;

    const int* __restrict__ adj = g_adj[rel];
    int s0 = g_off[rel][node], s1 = g_off[rel][node + 1];
    float4 a0 = make_float4(0.f, 0.f, 0.f, 0.f);
    float4 a1 = make_float4(0.f, 0.f, 0.f, 0.f);
    float4 a2 = make_float4(0.f, 0.f, 0.f, 0.f);
    float4 a3 = make_float4(0.f, 0.f, 0.f, 0.f);
    int e = s0;
    for (; e + 3 < s1; e += 4) {
        int i0 = __ldg(&adj[e]);
        int i1 = __ldg(&adj[e + 1]);
        int i2 = __ldg(&adj[e + 2]);
        int i3 = __ldg(&adj[e + 3]);
        float4 v0 = *(const float4*)(xs + (size_t)i0 * DIMN + lane * 4);
        float4 v1 = *(const float4*)(xs + (size_t)i1 * DIMN + lane * 4);
        float4 v2 = *(const float4*)(xs + (size_t)i2 * DIMN + lane * 4);
        float4 v3 = *(const float4*)(xs + (size_t)i3 * DIMN + lane * 4);
        a0.x += v0.x; a0.y += v0.y; a0.z += v0.z; a0.w += v0.w;
        a1.x += v1.x; a1.y += v1.y; a1.z += v1.z; a1.w += v1.w;
        a2.x += v2.x; a2.y += v2.y; a2.z += v2.z; a2.w += v2.w;
        a3.x += v3.x; a3.y += v3.y; a3.z += v3.z; a3.w += v3.w;
    }
    for (; e < s1; e++) {
        int i0 = __ldg(&adj[e]);
        float4 v0 = *(const float4*)(xs + (size_t)i0 * DIMN + lane * 4);
        a0.x += v0.x; a0.y += v0.y; a0.z += v0.z; a0.w += v0.w;
    }
    a0.x += a1.x + a2.x + a3.x;
    a0.y += a1.y + a2.y + a3.y;
    a0.z += a1.z + a2.z + a3.z;
    a0.w += a1.w + a2.w + a3.w;
    int deg = s1 - s0;
    float inv = 1.0f / (float)(deg > 0 ? deg : 1);
    a0.x *= inv; a0.y *= inv; a0.z *= inv; a0.w *= inv;
    *(float4*)(mean + (size_t)node * DIMN + lane * 4) = a0;
}

// ---------------- mma.sync helpers ----------------
__device__ __forceinline__ uint32_t smem_u32(const void* p) {
    uint32_t a;
    asm("{ .reg .u64 t; cvta.to.shared.u64 t, %1; cvt.u32.u64 %0, t; }"
        : "=r"(a) : "l"(p));
    return a;
}
__device__ __forceinline__ void ldsm4(uint32_t* r, uint32_t addr) {
    asm volatile("ldmatrix.sync.aligned.m8n8.x4.shared.b16 {%0,%1,%2,%3}, [%4];"
                 : "=r"(r[0]), "=r"(r[1]), "=r"(r[2]), "=r"(r[3]) : "r"(addr));
}
__device__ __forceinline__ void mma16816(float* d, const uint32_t* a,
                                         uint32_t b0, uint32_t b1) {
    asm volatile(
        "mma.sync.aligned.m16n8k16.row.col.f32.bf16.bf16.f32 "
        "{%0,%1,%2,%3}, {%4,%5,%6,%7}, {%8,%9}, {%0,%1,%2,%3};"
        : "+f"(d[0]), "+f"(d[1]), "+f"(d[2]), "+f"(d[3])
        : "r"(a[0]), "r"(a[1]), "r"(a[2]), "r"(a[3]), "r"(b0), "r"(b1));
}
__device__ __forceinline__ void cpa16(uint32_t dst, const void* src) {
    asm volatile("cp.async.ca.shared.global [%0], [%1], 16;"
                 :: "r"(dst), "l"(src) : "memory");
}
// zero-fill variant: src-size register (0 => fill 16B with zeros)
__device__ __forceinline__ void cpa16z(uint32_t dst, const void* src, int sz) {
    asm volatile("cp.async.ca.shared.global [%0], [%1], 16, %2;"
                 :: "r"(dst), "l"(src), "r"(sz) : "memory");
}
#define CPA_COMMIT() asm volatile("cp.async.commit_group;" ::: "memory")
#define CPA_WAIT0()  asm volatile("cp.async.wait_group 0;" ::: "memory")

// hi/lo bf16 split of a float2 into packed bf16x2 registers
__device__ __forceinline__ void split2(float2 v, uint32_t& h, uint32_t& l) {
    __nv_bfloat162 hb = __float22bfloat162_rn(v);
    float2 r = make_float2(v.x - __bfloat162float(__low2bfloat16(hb)),
                           v.y - __bfloat162float(__high2bfloat16(hb)));
    __nv_bfloat162 lb = __float22bfloat162_rn(r);
    h = *reinterpret_cast<uint32_t*>(&hb);
    l = *reinterpret_cast<uint32_t*>(&lb);
}

// ---------------- tensor-core GEMM: double-buffered fp32 A, frags from smem ----------------
#define TSTRIDE 72        // W tile row stride (bf16 elems); 144 B
#define ASTRIDE 68        // A fp32 tile row stride (floats); 272 B, 16B-aligned
#define A_TILE_B (128 * ASTRIDE * 4)          // 34816 B per stage
#define W_HALF_B (128 * TSTRIDE * 2)          // 18432 B per half

__global__ void __launch_bounds__(256, 2)
k_gemm_mma(const float* __restrict__ xu, const float* __restrict__ xi,
           float* __restrict__ out_user, float* __restrict__ out_item,
           int NU, int NI, int blocksU)
{
    extern __shared__ float smemf[];
    float* Af0 = smemf;                               // stage 0 fp32 A
    float* Af1 = smemf + 128 * ASTRIDE;               // stage 1 fp32 A
    uint32_t sWh = smem_u32(smemf) + 2 * A_TILE_B;    // W hi tile
    uint32_t sWl = sWh + W_HALF_B;                    // W lo tile
    uint32_t sAf0 = smem_u32(Af0);
    uint32_t sAf1 = smem_u32(Af1);

    int tid = threadIdx.x, w = tid >> 5, lane = tid & 31;
    int wm = w & 3;          // m-strip: rows [wm*32, wm*32+32)
    int wn = w >> 2;         // n-half:  cols [wn*64, wn*64+64)
    bool isU = (int)blockIdx.x < blocksU;
    int bidl = isU ? blockIdx.x : (blockIdx.x - blocksU);
    int m0 = bidl * 128;
    int M  = isU ? NU : NI;
    int nc = isU ? 4 : 6;
    const float* Achk[6];
    const __nv_bfloat16* WHp[6];
    const __nv_bfloat16* WLp[6];
    int coff[6];
    {
        const float* Ap[3];
        int wp[3];
        int np = isU ? 2 : 3;
        if (isU) { Ap[0] = g_meanR; Ap[1] = xu; Ap[2] = xu; wp[0] = 0; wp[1] = 1; wp[2] = 1; }
        else     { Ap[0] = g_meanB; Ap[1] = g_meanT; Ap[2] = xi; wp[0] = 2; wp[1] = 3; wp[2] = 4; }
        for (int p = 0; p < np; p++)
            for (int c = 0; c < 2; c++) {
                int ci = p * 2 + c;
                Achk[ci] = Ap[p];
                WHp[ci] = g_Wsp[wp[p]][0];
                WLp[ci] = g_Wsp[wp[p]][1];
                coff[ci] = c * 64;
            }
    }
    float* Cout = isU ? out_user : out_item;
    const float* bias = isU ? g_biasU : g_biasI;

    float acc[2][8][4];
    #pragma unroll
    for (int s = 0; s < 2; s++)
        #pragma unroll
        for (int i = 0; i < 8; i++)
            #pragma unroll
            for (int j = 0; j < 4; j++) acc[s][i][j] = 0.f;

    int g  = lane >> 2;           // A frag group row
    int t2 = (lane & 3) * 2;      // A frag k pair
    int b_n  = (lane & 7) + ((lane >> 4) << 3);
    int b_kh = ((lane >> 3) & 1) << 3;

    // per-thread cp.async A mapping: 8 x 16B segments
    int arow = tid >> 1;                 // not used; explicit per-it below

    // ---- prologue: prefetch A(0) into stage0 and W(0)
    {
        const float* A = Achk[0];
        #pragma unroll
        for (int it = 0; it < 8; it++) {
            int q = tid + it * 256;          // 0..2047
            int row = q >> 4;                // 0..127
            int seg = q & 15;                // 16B segment within 64-float chunk row
            int grow = m0 + row;
            int sz = (grow < M) ? 16 : 0;
            int srow = (grow < M) ? grow : (M - 1);
            cpa16z(sAf0 + (uint32_t)(row * ASTRIDE + seg * 4) * 4,
                   A + (size_t)srow * DIMN + coff[0] + seg * 4, sz);
        }
        #pragma unroll
        for (int it = 0; it < 4; it++) {
            int q = tid + it * 256;
            int n = q >> 3;
            int j = q & 7;
            cpa16(sWh + (uint32_t)(n * TSTRIDE + j * 8) * 2, WHp[0] + n * 128 + coff[0] + j * 8);
            cpa16(sWl + (uint32_t)(n * TSTRIDE + j * 8) * 2, WLp[0] + n * 128 + coff[0] + j * 8);
        }
        CPA_COMMIT();
    }
    (void)arow;

    for (int ci = 0; ci < nc; ci++) {
        uint32_t sAcur = (ci & 1) ? sAf1 : sAf0;
        uint32_t sAnxt = (ci & 1) ? sAf0 : sAf1;
        const float* Afc = (ci & 1) ? Af1 : Af0;

        CPA_WAIT0();
        __syncthreads();             // tiles visible; prev compute done by all

        // prefetch A(ci+1) into the other stage (overlaps compute below)
        if (ci + 1 < nc) {
            const float* A = Achk[ci + 1];
            #pragma unroll
            for (int it = 0; it < 8; it++) {
                int q = tid + it * 256;
                int row = q >> 4;
                int seg = q & 15;
                int grow = m0 + row;
                int sz = (grow < M) ? 16 : 0;
                int srow = (grow < M) ? grow : (M - 1);
                cpa16z(sAnxt + (uint32_t)(row * ASTRIDE + seg * 4) * 4,
                       A + (size_t)srow * DIMN + coff[ci + 1] + seg * 4, sz);
            }
            CPA_COMMIT();
        }

        // ---- compute chunk ci: warp (wm, wn) owns m32 x n64
        #pragma unroll
        for (int ks = 0; ks < 4; ks++) {
            uint32_t aH[2][4], aL[2][4];
            #pragma unroll
            for (int s = 0; s < 2; s++) {
                int r0 = wm * 32 + s * 16 + g;
                int r1 = r0 + 8;
                int kc = ks * 16 + t2;
                float2 p0 = *(const float2*)(Afc + r0 * ASTRIDE + kc);
                float2 p1 = *(const float2*)(Afc + r1 * ASTRIDE + kc);
                float2 p2 = *(const float2*)(Afc + r0 * ASTRIDE + kc + 8);
                float2 p3 = *(const float2*)(Afc + r1 * ASTRIDE + kc + 8);
                split2(p0, aH[s][0], aL[s][0]);
                split2(p1, aH[s][1], aL[s][1]);
                split2(p2, aH[s][2], aL[s][2]);
                split2(p3, aH[s][3], aL[s][3]);
            }
            #pragma unroll
            for (int nt = 0; nt < 4; nt++) {
                uint32_t bH[4], bL[4];
                uint32_t boff = (uint32_t)((wn * 64 + nt * 16 + b_n) * TSTRIDE
                                           + ks * 16 + b_kh) * 2;
                ldsm4(bH, sWh + boff);
                ldsm4(bL, sWl + boff);
                #pragma unroll
                for (int s = 0; s < 2; s++) {
                    mma16816(acc[s][nt * 2],     aH[s], bH[0], bH[1]);
                    mma16816(acc[s][nt * 2 + 1], aH[s], bH[2], bH[3]);
                    mma16816(acc[s][nt * 2],     aH[s], bL[0], bL[1]);
                    mma16816(acc[s][nt * 2 + 1], aH[s], bL[2], bL[3]);
                    mma16816(acc[s][nt * 2],     aL[s], bH[0], bH[1]);
                    mma16816(acc[s][nt * 2 + 1], aL[s], bH[2], bH[3]);
                }
            }
        }

        __syncthreads();             // all warps done reading W tile
        // prefetch W(ci+1) into the (single) W buffer
        if (ci + 1 < nc) {
            #pragma unroll
            for (int it = 0; it < 4; it++) {
                int q = tid + it * 256;
                int n = q >> 3;
                int j = q & 7;
                cpa16(sWh + (uint32_t)(n * TSTRIDE + j * 8) * 2,
                      WHp[ci + 1] + n * 128 + coff[ci + 1] + j * 8);
                cpa16(sWl + (uint32_t)(n * TSTRIDE + j * 8) * 2,
                      WLp[ci + 1] + n * 128 + coff[ci + 1] + j * 8);
            }
            CPA_COMMIT();
        }
        (void)sAcur;
    }

    // ---- epilogue
    int ncol = (lane & 3) * 2;
    #pragma unroll
    for (int s = 0; s < 2; s++) {
        int row0 = m0 + wm * 32 + s * 16 + (lane >> 2);
        int row1 = row0 + 8;
        #pragma unroll
        for (int t8 = 0; t8 < 8; t8++) {
            int n = wn * 64 + t8 * 8 + ncol;
            float2 bv = *(const float2*)(bias + n);
            if (row0 < M) {
                float2 o = make_float2(acc[s][t8][0] + bv.x, acc[s][t8][1] + bv.y);
                *(float2*)(Cout + (size_t)row0 * DIMN + n) = o;
            }
            if (row1 < M) {
                float2 o = make_float2(acc[s][t8][2] + bv.x, acc[s][t8][3] + bv.y);
                *(float2*)(Cout + (size_t)row1 * DIMN + n) = o;
            }
        }
    }
}

// ---------------- launch ----------------
extern "C" void kernel_launch(void* const* d_in, const int* in_sizes, int n_in,
                              void* d_out, int out_size) {
    const float* xu  = (const float*)d_in[0];
    const float* xi  = (const float*)d_in[1];
    const float* xt  = (const float*)d_in[2];
    const int*   eb  = (const int*)d_in[3];
    const int*   er  = (const int*)d_in[4];
    const int*   et  = (const int*)d_in[5];
    const float* WlB = (const float*)d_in[6];
    const float* WrB = (const float*)d_in[7];
    const float* bB  = (const float*)d_in[8];
    const float* WlR = (const float*)d_in[9];
    const float* WrR = (const float*)d_in[10];
    const float* bR  = (const float*)d_in[11];
    const float* WlT = (const float*)d_in[12];
    const float* WrT = (const float*)d_in[13];
    const float* bT  = (const float*)d_in[14];

    int NU = in_sizes[0] / DIMN;
    int NI = in_sizes[1] / DIMN;
    int EB = in_sizes[3] / 2;
    int ER = in_sizes[4] / 2;
    int ET = in_sizes[5] / 2;

    float* out_user = (float*)d_out;
    float* out_item = (float*)d_out + (size_t)NU * DIMN;

    int Etot = EB + ER + ET;

    k_init<<<(3 * (NU_MAX + 1) + 255) / 256, 256>>>(WlR, WrR, WlB, WlT, WrB, WrT,
                                                    bR, bB, bT);
    k_hist3<<<(Etot / 2 + 256) / 256, 256>>>(eb + EB, er + ER, et + ET, EB, ER, ET);
    k_scan<<<3, 1024>>>(NI, NU, NI);
    k_fill3<<<(Etot / 2 + 256) / 256, 256>>>(eb, er, et, EB, ER, ET);

    int totalNodes = NI + NU + NI;
    k_agg3<<<(totalNodes * 32 + 255) / 256, 256>>>(xu, xi, xt, NU, NI);

    const int SMEM_BYTES = 2 * A_TILE_B + 2 * W_HALF_B;   // 69632 + 36864 = 106496
    cudaFuncSetAttribute(k_gemm_mma, cudaFuncAttributeMaxDynamicSharedMemorySize, SMEM_BYTES);
    int blocksU = (NU + 127) / 128;
    int blocksI = (NI + 127) / 128;
    k_gemm_mma<<<blocksU + blocksI, 256, SMEM_BYTES>>>(xu, xi, out_user, out_item,
                                                       NU, NI, blocksU);
}

// round 12
// speedup vs baseline: 1.1028x; 1.1028x over previous
#include <cuda_runtime.h>
#include <cuda_bf16.h>
#include <cstddef>
#include <cstdint>

#define NU_MAX 100000
#define NI_MAX 100000
#define E_MAX  1000000
#define DIMN   128

// ---------------- scratch (static __device__, no allocation) ----------------
__device__ int   g_cnt[3][NU_MAX + 1];
__device__ int   g_off[3][NU_MAX + 1];
__device__ int   g_cur[3][NU_MAX];
__device__ int   g_adj[3][E_MAX];
__device__ float g_meanB[(size_t)NI_MAX * DIMN];
__device__ float g_meanR[(size_t)NU_MAX * DIMN];
__device__ float g_meanT[(size_t)NI_MAX * DIMN];

// split + transposed weights: [panel][half hi/lo][n*128+k] bf16
__device__ __align__(16) __nv_bfloat16 g_Wsp[5][2][DIMN * DIMN];
__device__ __align__(16) float g_biasU[DIMN];
__device__ __align__(16) float g_biasI[DIMN];

// ---------------- host-side streams/events (created once, before capture) ----
namespace {
struct StreamKit {
    cudaStream_t sA, sB;
    cudaEvent_t ev0, evA, evB;
    StreamKit() {
        cudaStreamCreateWithFlags(&sA, cudaStreamNonBlocking);
        cudaStreamCreateWithFlags(&sB, cudaStreamNonBlocking);
        cudaEventCreateWithFlags(&ev0, cudaEventDisableTiming);
        cudaEventCreateWithFlags(&evA, cudaEventDisableTiming);
        cudaEventCreateWithFlags(&evB, cudaEventDisableTiming);
    }
};
StreamKit g_sk;
}

// ---------------- init: zero counters + weight prep (merged) ----------------
__global__ void k_init(const float* __restrict__ WlR, const float* __restrict__ WrR,
                       const float* __restrict__ WlB, const float* __restrict__ WlT,
                       const float* __restrict__ WrB, const float* __restrict__ WrT,
                       const float* __restrict__ bR, const float* __restrict__ bB,
                       const float* __restrict__ bT) {
    int i = blockIdx.x * blockDim.x + threadIdx.x;
    const int total = 3 * (NU_MAX + 1);
    if (i < total) ((int*)g_cnt)[i] = 0;
    if (i < 5 * 16384) {
        int panel = i >> 14;
        int e = i & 16383;
        int k = e >> 7;
        int n = e & 127;
        float v;
        switch (panel) {
            case 0:  v = WlR[k * 128 + n]; break;
            case 1:  v = WrR[k * 128 + n]; break;
            case 2:  v = 0.5f * WlB[k * 128 + n]; break;
            case 3:  v = 0.5f * WlT[k * 128 + n]; break;
            default: v = 0.5f * (WrB[k * 128 + n] + WrT[k * 128 + n]);
        }
        __nv_bfloat16 h = __float2bfloat16_rn(v);
        __nv_bfloat16 l = __float2bfloat16_rn(v - __bfloat162float(h));
        g_Wsp[panel][0][n * 128 + k] = h;
        g_Wsp[panel][1][n * 128 + k] = l;
    }
    if (i < DIMN) {
        g_biasU[i] = bR[i];
        g_biasI[i] = 0.5f * (bB[i] + bT[i]);
    }
}

// ---------------- CSR build: per-relation kernels (2 edges/thread) ----------
__global__ void k_hist1(const int* __restrict__ dst, int E, int rel) {
    int t = blockIdx.x * blockDim.x + threadIdx.x;
    #pragma unroll
    for (int j = 0; j < 2; j++) {
        int e = t * 2 + j;
        if (e < E) atomicAdd(&g_cnt[rel][dst[e]], 1);
    }
}

// scan up to 2 relations: blockIdx 0 -> (r0,n0), 1 -> (r1,n1)
__global__ void k_scan_pair(int r0, int n0, int r1, int n1) {
    int rel = (blockIdx.x == 0) ? r0 : r1;
    int n   = (blockIdx.x == 0) ? n0 : n1;
    int lane = threadIdx.x & 31, wid = threadIdx.x >> 5;
    __shared__ int wsum[32];
    __shared__ int carry;
    if (threadIdx.x == 0) carry = 0;
    __syncthreads();
    for (int base = 0; base < n; base += 1024) {
        int i = base + threadIdx.x;
        int v = (i < n) ? g_cnt[rel][i] : 0;
        int s = v;
        #pragma unroll
        for (int d = 1; d < 32; d <<= 1) {
            int t = __shfl_up_sync(0xFFFFFFFFu, s, d);
            if (lane >= d) s += t;
        }
        if (lane == 31) wsum[wid] = s;
        __syncthreads();
        if (wid == 0) {
            int w = wsum[lane];
            #pragma unroll
            for (int d = 1; d < 32; d <<= 1) {
                int t = __shfl_up_sync(0xFFFFFFFFu, w, d);
                if (lane >= d) w += t;
            }
            wsum[lane] = w;
        }
        __syncthreads();
        int woff = (wid > 0) ? wsum[wid - 1] : 0;
        int c = carry;
        int excl = c + woff + s - v;
        if (i < n) { g_off[rel][i] = excl; g_cur[rel][i] = excl; }
        int tot = wsum[31];
        __syncthreads();
        if (threadIdx.x == 0) carry = c + tot;
        __syncthreads();
    }
    if (threadIdx.x == 0) g_off[rel][n] = carry;
}

__global__ void k_fill1(const int* __restrict__ ei, int E, int rel) {
    int t = blockIdx.x * blockDim.x + threadIdx.x;
    #pragma unroll
    for (int j = 0; j < 2; j++) {
        int e = t * 2 + j;
        if (e < E) {
            int d = ei[E + e];
            int s = ei[e];
            int p = atomicAdd(&g_cur[rel][d], 1);
            g_adj[rel][p] = s;
        }
    }
}

// ---------------- mean aggregation: one relation, warp/node, unroll-4 ------
__global__ void k_agg1(const float* __restrict__ xs, float* __restrict__ mean,
                       int rel, int n_dst) {
    int node = (blockIdx.x * blockDim.x + threadIdx.x) >> 5;
    int lane = threadIdx.x & 31;
    if (node >= n_dst) return;

    const int* __restrict__ adj = g_adj[rel];
    int s0 = g_off[rel][node], s1 = g_off[rel][node + 1];
    float4 a0 = make_float4(0.f, 0.f, 0.f, 0.f);
    float4 a1 = make_float4(0.f, 0.f, 0.f, 0.f);
    float4 a2 = make_float4(0.f, 0.f, 0.f, 0.f);
    float4 a3 = make_float4(0.f, 0.f, 0.f, 0.f);
    int e = s0;
    for (; e + 3 < s1; e += 4) {
        int i0 = __ldg(&adj[e]);
        int i1 = __ldg(&adj[e + 1]);
        int i2 = __ldg(&adj[e + 2]);
        int i3 = __ldg(&adj[e + 3]);
        float4 v0 = *(const float4*)(xs + (size_t)i0 * DIMN + lane * 4);
        float4 v1 = *(const float4*)(xs + (size_t)i1 * DIMN + lane * 4);
        float4 v2 = *(const float4*)(xs + (size_t)i2 * DIMN + lane * 4);
        float4 v3 = *(const float4*)(xs + (size_t)i3 * DIMN + lane * 4);
        a0.x += v0.x; a0.y += v0.y; a0.z += v0.z; a0.w += v0.w;
        a1.x += v1.x; a1.y += v1.y; a1.z += v1.z; a1.w += v1.w;
        a2.x += v2.x; a2.y += v2.y; a2.z += v2.z; a2.w += v2.w;
        a3.x += v3.x; a3.y += v3.y; a3.z += v3.z; a3.w += v3.w;
    }
    for (; e < s1; e++) {
        int i0 = __ldg(&adj[e]);
        float4 v0 = *(const float4*)(xs + (size_t)i0 * DIMN + lane * 4);
        a0.x += v0.x; a0.y += v0.y; a0.z += v0.z; a0.w += v0.w;
    }
    a0.x += a1.x + a2.x + a3.x;
    a0.y += a1.y + a2.y + a3.y;
    a0.z += a1.z + a2.z + a3.z;
    a0.w += a1.w + a2.w + a3.w;
    int deg = s1 - s0;
    float inv = 1.0f / (float)(deg > 0 ? deg : 1);
    a0.x *= inv; a0.y *= inv; a0.z *= inv; a0.w *= inv;
    *(float4*)(mean + (size_t)node * DIMN + lane * 4) = a0;
}

// ---------------- mma.sync helpers ----------------
__device__ __forceinline__ uint32_t smem_u32(const void* p) {
    uint32_t a;
    asm("{ .reg .u64 t; cvta.to.shared.u64 t, %1; cvt.u32.u64 %0, t; }"
        : "=r"(a) : "l"(p));
    return a;
}
__device__ __forceinline__ void ldsm4(uint32_t* r, uint32_t addr) {
    asm volatile("ldmatrix.sync.aligned.m8n8.x4.shared.b16 {%0,%1,%2,%3}, [%4];"
                 : "=r"(r[0]), "=r"(r[1]), "=r"(r[2]), "=r"(r[3]) : "r"(addr));
}
__device__ __forceinline__ void mma16816(float* d, const uint32_t* a,
                                         uint32_t b0, uint32_t b1) {
    asm volatile(
        "mma.sync.aligned.m16n8k16.row.col.f32.bf16.bf16.f32 "
        "{%0,%1,%2,%3}, {%4,%5,%6,%7}, {%8,%9}, {%0,%1,%2,%3};"
        : "+f"(d[0]), "+f"(d[1]), "+f"(d[2]), "+f"(d[3])
        : "r"(a[0]), "r"(a[1]), "r"(a[2]), "r"(a[3]), "r"(b0), "r"(b1));
}
__device__ __forceinline__ void cpa16(uint32_t dst, const void* src) {
    asm volatile("cp.async.ca.shared.global [%0], [%1], 16;"
                 :: "r"(dst), "l"(src) : "memory");
}
#define CPA_COMMIT() asm volatile("cp.async.commit_group;" ::: "memory")
#define CPA_WAIT0()  asm volatile("cp.async.wait_group 0;" ::: "memory")

// ---------------- tensor-core GEMM core (round-9 2D warp tiling, exact) ----
#define TSTRIDE 72   // elements; 144 bytes

template <int NP>
__device__ __forceinline__ void gemm_core(const float* const* Ap, const int* wp,
                                          float* __restrict__ Cout,
                                          const float* __restrict__ bias,
                                          int M, int m0)
{
    extern __shared__ __nv_bfloat16 smem[];
    __nv_bfloat16* Ah = smem;
    __nv_bfloat16* Al = Ah + 128 * TSTRIDE;
    __nv_bfloat16* Wh = Al + 128 * TSTRIDE;
    __nv_bfloat16* Wl = Wh + 128 * TSTRIDE;
    const uint32_t sAh = smem_u32(Ah);
    const uint32_t sAl = smem_u32(Al);
    const uint32_t sWh = smem_u32(Wh);
    const uint32_t sWl = smem_u32(Wl);

    int tid = threadIdx.x, w = tid >> 5, lane = tid & 31;
    int wm = w & 3;          // m-strip: rows [wm*32, wm*32+32)
    int wn = w >> 2;         // n-half:  cols [wn*64, wn*64+64)

    float acc[2][8][4];
    #pragma unroll
    for (int s = 0; s < 2; s++)
        #pragma unroll
        for (int i = 0; i < 8; i++)
            #pragma unroll
            for (int j = 0; j < 4; j++) acc[s][i][j] = 0.f;

    int a_row = lane & 15;
    int a_kh  = (lane >> 4) << 3;
    int b_n   = (lane & 7) + ((lane >> 4) << 3);
    int b_kh  = ((lane >> 3) & 1) << 3;

    #pragma unroll
    for (int p = 0; p < NP; p++) {
        const float* A = Ap[p];
        const __nv_bfloat16* WHsrc = g_Wsp[wp[p]][0];
        const __nv_bfloat16* WLsrc = g_Wsp[wp[p]][1];
        for (int c = 0; c < 2; c++) {
            __syncthreads();   // protect previous iteration's smem reads
            // ---- W chunk via cp.async (overlaps with A convert below)
            #pragma unroll
            for (int it = 0; it < 4; it++) {
                int q = tid + it * 256;
                int n = q >> 3;
                int j = q & 7;
                cpa16(sWh + (n * TSTRIDE + j * 8) * 2, WHsrc + n * 128 + c * 64 + j * 8);
                cpa16(sWl + (n * TSTRIDE + j * 8) * 2, WLsrc + n * 128 + c * 64 + j * 8);
            }
            CPA_COMMIT();
            // ---- load & split A chunk [128 m x 64 k]
            #pragma unroll
            for (int it = 0; it < 8; it++) {
                int q = tid + it * 256;
                int row = q >> 4;
                int k4  = (q & 15) << 2;
                int grow = m0 + row;
                float4 v = make_float4(0.f, 0.f, 0.f, 0.f);
                if (grow < M) v = *(const float4*)(A + (size_t)grow * DIMN + c * 64 + k4);
                __nv_bfloat16 h0 = __float2bfloat16_rn(v.x);
                __nv_bfloat16 h1 = __float2bfloat16_rn(v.y);
                __nv_bfloat16 h2 = __float2bfloat16_rn(v.z);
                __nv_bfloat16 h3 = __float2bfloat16_rn(v.w);
                ushort4 uh = make_ushort4(__bfloat16_as_ushort(h0), __bfloat16_as_ushort(h1),
                                          __bfloat16_as_ushort(h2), __bfloat16_as_ushort(h3));
                __nv_bfloat16 l0 = __float2bfloat16_rn(v.x - __bfloat162float(h0));
                __nv_bfloat16 l1 = __float2bfloat16_rn(v.y - __bfloat162float(h1));
                __nv_bfloat16 l2 = __float2bfloat16_rn(v.z - __bfloat162float(h2));
                __nv_bfloat16 l3 = __float2bfloat16_rn(v.w - __bfloat162float(h3));
                ushort4 ul = make_ushort4(__bfloat16_as_ushort(l0), __bfloat16_as_ushort(l1),
                                          __bfloat16_as_ushort(l2), __bfloat16_as_ushort(l3));
                *(ushort4*)(Ah + row * TSTRIDE + k4) = uh;
                *(ushort4*)(Al + row * TSTRIDE + k4) = ul;
            }
            CPA_WAIT0();
            __syncthreads();
            // ---- compute: warp (wm, wn) owns m32 x n64
            #pragma unroll
            for (int ks = 0; ks < 4; ks++) {
                uint32_t aH[2][4], aL[2][4];
                #pragma unroll
                for (int s = 0; s < 2; s++) {
                    uint32_t aoff = (uint32_t)((wm * 32 + s * 16 + a_row) * TSTRIDE
                                               + ks * 16 + a_kh) * 2;
                    ldsm4(aH[s], sAh + aoff);
                    ldsm4(aL[s], sAl + aoff);
                }
                #pragma unroll
                for (int nt = 0; nt < 4; nt++) {
                    uint32_t bH[4], bL[4];
                    uint32_t boff = (uint32_t)((wn * 64 + nt * 16 + b_n) * TSTRIDE
                                               + ks * 16 + b_kh) * 2;
                    ldsm4(bH, sWh + boff);
                    ldsm4(bL, sWl + boff);
                    #pragma unroll
                    for (int s = 0; s < 2; s++) {
                        mma16816(acc[s][nt * 2],     aH[s], bH[0], bH[1]);
                        mma16816(acc[s][nt * 2 + 1], aH[s], bH[2], bH[3]);
                        mma16816(acc[s][nt * 2],     aH[s], bL[0], bL[1]);
                        mma16816(acc[s][nt * 2 + 1], aH[s], bL[2], bL[3]);
                        mma16816(acc[s][nt * 2],     aL[s], bH[0], bH[1]);
                        mma16816(acc[s][nt * 2 + 1], aL[s], bH[2], bH[3]);
                    }
                }
            }
        }
    }

    // ---- epilogue
    int ncol = (lane & 3) * 2;
    #pragma unroll
    for (int s = 0; s < 2; s++) {
        int row0 = m0 + wm * 32 + s * 16 + (lane >> 2);
        int row1 = row0 + 8;
        #pragma unroll
        for (int t8 = 0; t8 < 8; t8++) {
            int n = wn * 64 + t8 * 8 + ncol;
            float2 bv = *(const float2*)(bias + n);
            if (row0 < M) {
                float2 o = make_float2(acc[s][t8][0] + bv.x, acc[s][t8][1] + bv.y);
                *(float2*)(Cout + (size_t)row0 * DIMN + n) = o;
            }
            if (row1 < M) {
                float2 o = make_float2(acc[s][t8][2] + bv.x, acc[s][t8][3] + bv.y);
                *(float2*)(Cout + (size_t)row1 * DIMN + n) = o;
            }
        }
    }
}

__global__ void __launch_bounds__(256, 2)
k_gemm_user(const float* __restrict__ xu, float* __restrict__ out, int NU) {
    const float* Ap[2] = {g_meanR, xu};
    const int wp[2] = {0, 1};
    gemm_core<2>(Ap, wp, out, g_biasU, NU, blockIdx.x * 128);
}

__global__ void __launch_bounds__(256, 2)
k_gemm_item(const float* __restrict__ xi, float* __restrict__ out, int NI) {
    const float* Ap[3] = {g_meanB, g_meanT, xi};
    const int wp[3] = {2, 3, 4};
    gemm_core<3>(Ap, wp, out, g_biasI, NI, blockIdx.x * 128);
}

// ---------------- launch: two-stream pipelined graph ----------------
extern "C" void kernel_launch(void* const* d_in, const int* in_sizes, int n_in,
                              void* d_out, int out_size) {
    const float* xu  = (const float*)d_in[0];
    const float* xi  = (const float*)d_in[1];
    const float* xt  = (const float*)d_in[2];
    const int*   eb  = (const int*)d_in[3];
    const int*   er  = (const int*)d_in[4];
    const int*   et  = (const int*)d_in[5];
    const float* WlB = (const float*)d_in[6];
    const float* WrB = (const float*)d_in[7];
    const float* bB  = (const float*)d_in[8];
    const float* WlR = (const float*)d_in[9];
    const float* WrR = (const float*)d_in[10];
    const float* bR  = (const float*)d_in[11];
    const float* WlT = (const float*)d_in[12];
    const float* WrT = (const float*)d_in[13];
    const float* bT  = (const float*)d_in[14];

    int NU = in_sizes[0] / DIMN;
    int NI = in_sizes[1] / DIMN;
    int EB = in_sizes[3] / 2;
    int ER = in_sizes[4] / 2;
    int ET = in_sizes[5] / 2;

    float* out_user = (float*)d_out;
    float* out_item = (float*)d_out + (size_t)NU * DIMN;

    float* dmB; cudaGetSymbolAddress((void**)&dmB, g_meanB);
    float* dmR; cudaGetSymbolAddress((void**)&dmR, g_meanR);
    float* dmT; cudaGetSymbolAddress((void**)&dmT, g_meanT);

    const int SMEM_BYTES = 4 * 128 * TSTRIDE * 2;   // 73728
    cudaFuncSetAttribute(k_gemm_user, cudaFuncAttributeMaxDynamicSharedMemorySize, SMEM_BYTES);
    cudaFuncSetAttribute(k_gemm_item, cudaFuncAttributeMaxDynamicSharedMemorySize, SMEM_BYTES);

    cudaStream_t s0 = 0;  // capture-origin (legacy) stream

    // init: zero counters + weight prep, then fork
    k_init<<<(3 * (NU_MAX + 1) + 255) / 256, 256, 0, s0>>>(WlR, WrR, WlB, WlT,
                                                           WrB, WrT, bR, bB, bT);
    cudaEventRecord(g_sk.ev0, s0);
    cudaStreamWaitEvent(g_sk.sA, g_sk.ev0, 0);
    cudaStreamWaitEvent(g_sk.sB, g_sk.ev0, 0);

    // ---- stream A: rel 1 (rev) -> out_user
    k_hist1<<<(ER / 2 + 255) / 256, 256, 0, g_sk.sA>>>(er + ER, ER, 1);
    k_scan_pair<<<1, 1024, 0, g_sk.sA>>>(1, NU, 1, NU);
    k_fill1<<<(ER / 2 + 255) / 256, 256, 0, g_sk.sA>>>(er, ER, 1);
    k_agg1<<<(NU * 32 + 255) / 256, 256, 0, g_sk.sA>>>(xi, dmR, 1, NU);
    k_gemm_user<<<(NU + 127) / 128, 256, SMEM_BYTES, g_sk.sA>>>(xu, out_user, NU);
    cudaEventRecord(g_sk.evA, g_sk.sA);

    // ---- stream B: rels 0 (buys), 2 (tags) -> out_item
    k_hist1<<<(EB / 2 + 255) / 256, 256, 0, g_sk.sB>>>(eb + EB, EB, 0);
    k_hist1<<<(ET / 2 + 255) / 256, 256, 0, g_sk.sB>>>(et + ET, ET, 2);
    k_scan_pair<<<2, 1024, 0, g_sk.sB>>>(0, NI, 2, NI);
    k_fill1<<<(EB / 2 + 255) / 256, 256, 0, g_sk.sB>>>(eb, EB, 0);
    k_fill1<<<(ET / 2 + 255) / 256, 256, 0, g_sk.sB>>>(et, ET, 2);
    k_agg1<<<(NI * 32 + 255) / 256, 256, 0, g_sk.sB>>>(xu, dmB, 0, NI);
    k_agg1<<<(NI * 32 + 255) / 256, 256, 0, g_sk.sB>>>(xt, dmT, 2, NI);
    k_gemm_item<<<(NI + 127) / 128, 256, SMEM_BYTES, g_sk.sB>>>(xi, out_item, NI);
    cudaEventRecord(g_sk.evB, g_sk.sB);

    // ---- join back to origin stream
    cudaStreamWaitEvent(s0, g_sk.evA, 0);
    cudaStreamWaitEvent(s0, g_sk.evB, 0);
}

// round 13
// speedup vs baseline: 1.1080x; 1.0048x over previous
#include <cuda_runtime.h>
#include <cuda_bf16.h>
#include <cuda_fp16.h>
#include <cstddef>
#include <cstdint>

#define NU_MAX 100000
#define NI_MAX 100000
#define E_MAX  1000000
#define DIMN   128

// ---------------- scratch (static __device__, no allocation) ----------------
__device__ int   g_cnt[3][NU_MAX + 1];
__device__ int   g_off[3][NU_MAX + 1];
__device__ int   g_cur[3][NU_MAX];
__device__ int   g_adj[3][E_MAX];
__device__ float g_meanB[(size_t)NI_MAX * DIMN];
__device__ float g_meanR[(size_t)NU_MAX * DIMN];
__device__ float g_meanT[(size_t)NI_MAX * DIMN];

// fp16 copies of node features for low-traffic gathering
__device__ __align__(16) __half g_xuh[(size_t)NU_MAX * DIMN];
__device__ __align__(16) __half g_xih[(size_t)NI_MAX * DIMN];
__device__ __align__(16) __half g_xth[(size_t)NU_MAX * DIMN];  // sized safe

// split + transposed weights: [panel][half hi/lo][n*128+k] bf16
__device__ __align__(16) __nv_bfloat16 g_Wsp[5][2][DIMN * DIMN];
__device__ __align__(16) float g_biasU[DIMN];
__device__ __align__(16) float g_biasI[DIMN];

// ---------------- host-side streams/events (created once, before capture) ----
namespace {
struct StreamKit {
    cudaStream_t sA, sB;
    cudaEvent_t ev0, evA, evB;
    StreamKit() {
        cudaStreamCreateWithFlags(&sA, cudaStreamNonBlocking);
        cudaStreamCreateWithFlags(&sB, cudaStreamNonBlocking);
        cudaEventCreateWithFlags(&ev0, cudaEventDisableTiming);
        cudaEventCreateWithFlags(&evA, cudaEventDisableTiming);
        cudaEventCreateWithFlags(&evB, cudaEventDisableTiming);
    }
};
StreamKit g_sk;
}

// ---------------- init: zero counters + weight prep (merged) ----------------
__global__ void k_init(const float* __restrict__ WlR, const float* __restrict__ WrR,
                       const float* __restrict__ WlB, const float* __restrict__ WlT,
                       const float* __restrict__ WrB, const float* __restrict__ WrT,
                       const float* __restrict__ bR, const float* __restrict__ bB,
                       const float* __restrict__ bT) {
    int i = blockIdx.x * blockDim.x + threadIdx.x;
    const int total = 3 * (NU_MAX + 1);
    if (i < total) ((int*)g_cnt)[i] = 0;
    if (i < 5 * 16384) {
        int panel = i >> 14;
        int e = i & 16383;
        int k = e >> 7;
        int n = e & 127;
        float v;
        switch (panel) {
            case 0:  v = WlR[k * 128 + n]; break;
            case 1:  v = WrR[k * 128 + n]; break;
            case 2:  v = 0.5f * WlB[k * 128 + n]; break;
            case 3:  v = 0.5f * WlT[k * 128 + n]; break;
            default: v = 0.5f * (WrB[k * 128 + n] + WrT[k * 128 + n]);
        }
        __nv_bfloat16 h = __float2bfloat16_rn(v);
        __nv_bfloat16 l = __float2bfloat16_rn(v - __bfloat162float(h));
        g_Wsp[panel][0][n * 128 + k] = h;
        g_Wsp[panel][1][n * 128 + k] = l;
    }
    if (i < DIMN) {
        g_biasU[i] = bR[i];
        g_biasI[i] = 0.5f * (bB[i] + bT[i]);
    }
}

// ---------------- fp32 -> fp16 feature conversion ----------------
__global__ void k_tohalf(const float* __restrict__ x, __half* __restrict__ xh, int n) {
    int i = (blockIdx.x * blockDim.x + threadIdx.x) * 4;
    if (i < n) {
        float4 v = *(const float4*)(x + i);
        __half2 a = __floats2half2_rn(v.x, v.y);
        __half2 b = __floats2half2_rn(v.z, v.w);
        uint2 u;
        u.x = *reinterpret_cast<uint32_t*>(&a);
        u.y = *reinterpret_cast<uint32_t*>(&b);
        *(uint2*)(xh + i) = u;
    }
}

// ---------------- CSR build: per-relation kernels (2 edges/thread) ----------
__global__ void k_hist1(const int* __restrict__ dst, int E, int rel) {
    int t = blockIdx.x * blockDim.x + threadIdx.x;
    #pragma unroll
    for (int j = 0; j < 2; j++) {
        int e = t * 2 + j;
        if (e < E) atomicAdd(&g_cnt[rel][dst[e]], 1);
    }
}

// scan up to 2 relations: blockIdx 0 -> (r0,n0), 1 -> (r1,n1)
__global__ void k_scan_pair(int r0, int n0, int r1, int n1) {
    int rel = (blockIdx.x == 0) ? r0 : r1;
    int n   = (blockIdx.x == 0) ? n0 : n1;
    int lane = threadIdx.x & 31, wid = threadIdx.x >> 5;
    __shared__ int wsum[32];
    __shared__ int carry;
    if (threadIdx.x == 0) carry = 0;
    __syncthreads();
    for (int base = 0; base < n; base += 1024) {
        int i = base + threadIdx.x;
        int v = (i < n) ? g_cnt[rel][i] : 0;
        int s = v;
        #pragma unroll
        for (int d = 1; d < 32; d <<= 1) {
            int t = __shfl_up_sync(0xFFFFFFFFu, s, d);
            if (lane >= d) s += t;
        }
        if (lane == 31) wsum[wid] = s;
        __syncthreads();
        if (wid == 0) {
            int w = wsum[lane];
            #pragma unroll
            for (int d = 1; d < 32; d <<= 1) {
                int t = __shfl_up_sync(0xFFFFFFFFu, w, d);
                if (lane >= d) w += t;
            }
            wsum[lane] = w;
        }
        __syncthreads();
        int woff = (wid > 0) ? wsum[wid - 1] : 0;
        int c = carry;
        int excl = c + woff + s - v;
        if (i < n) { g_off[rel][i] = excl; g_cur[rel][i] = excl; }
        int tot = wsum[31];
        __syncthreads();
        if (threadIdx.x == 0) carry = c + tot;
        __syncthreads();
    }
    if (threadIdx.x == 0) g_off[rel][n] = carry;
}

__global__ void k_fill1(const int* __restrict__ ei, int E, int rel) {
    int t = blockIdx.x * blockDim.x + threadIdx.x;
    #pragma unroll
    for (int j = 0; j < 2; j++) {
        int e = t * 2 + j;
        if (e < E) {
            int d = ei[E + e];
            int s = ei[e];
            int p = atomicAdd(&g_cur[rel][d], 1);
            g_adj[rel][p] = s;
        }
    }
}

// ---------------- mean aggregation: fp16 gather, fp32 accumulate ------------
__global__ void k_agg1(const __half* __restrict__ xs, float* __restrict__ mean,
                       int rel, int n_dst) {
    int node = (blockIdx.x * blockDim.x + threadIdx.x) >> 5;
    int lane = threadIdx.x & 31;
    if (node >= n_dst) return;

    const int* __restrict__ adj = g_adj[rel];
    int s0 = g_off[rel][node], s1 = g_off[rel][node + 1];
    float4 a0 = make_float4(0.f, 0.f, 0.f, 0.f);
    float4 a1 = make_float4(0.f, 0.f, 0.f, 0.f);
    float4 a2 = make_float4(0.f, 0.f, 0.f, 0.f);
    float4 a3 = make_float4(0.f, 0.f, 0.f, 0.f);
    int e = s0;
    for (; e + 3 < s1; e += 4) {
        int i0 = __ldg(&adj[e]);
        int i1 = __ldg(&adj[e + 1]);
        int i2 = __ldg(&adj[e + 2]);
        int i3 = __ldg(&adj[e + 3]);
        uint2 u0 = *(const uint2*)(xs + (size_t)i0 * DIMN + lane * 4);
        uint2 u1 = *(const uint2*)(xs + (size_t)i1 * DIMN + lane * 4);
        uint2 u2 = *(const uint2*)(xs + (size_t)i2 * DIMN + lane * 4);
        uint2 u3 = *(const uint2*)(xs + (size_t)i3 * DIMN + lane * 4);
        float2 p, q;
        p = __half22float2(*reinterpret_cast<__half2*>(&u0.x));
        q = __half22float2(*reinterpret_cast<__half2*>(&u0.y));
        a0.x += p.x; a0.y += p.y; a0.z += q.x; a0.w += q.y;
        p = __half22float2(*reinterpret_cast<__half2*>(&u1.x));
        q = __half22float2(*reinterpret_cast<__half2*>(&u1.y));
        a1.x += p.x; a1.y += p.y; a1.z += q.x; a1.w += q.y;
        p = __half22float2(*reinterpret_cast<__half2*>(&u2.x));
        q = __half22float2(*reinterpret_cast<__half2*>(&u2.y));
        a2.x += p.x; a2.y += p.y; a2.z += q.x; a2.w += q.y;
        p = __half22float2(*reinterpret_cast<__half2*>(&u3.x));
        q = __half22float2(*reinterpret_cast<__half2*>(&u3.y));
        a3.x += p.x; a3.y += p.y; a3.z += q.x; a3.w += q.y;
    }
    for (; e < s1; e++) {
        int i0 = __ldg(&adj[e]);
        uint2 u0 = *(const uint2*)(xs + (size_t)i0 * DIMN + lane * 4);
        float2 p = __half22float2(*reinterpret_cast<__half2*>(&u0.x));
        float2 q = __half22float2(*reinterpret_cast<__half2*>(&u0.y));
        a0.x += p.x; a0.y += p.y; a0.z += q.x; a0.w += q.y;
    }
    a0.x += a1.x + a2.x + a3.x;
    a0.y += a1.y + a2.y + a3.y;
    a0.z += a1.z + a2.z + a3.z;
    a0.w += a1.w + a2.w + a3.w;
    int deg = s1 - s0;
    float inv = 1.0f / (float)(deg > 0 ? deg : 1);
    a0.x *= inv; a0.y *= inv; a0.z *= inv; a0.w *= inv;
    *(float4*)(mean + (size_t)node * DIMN + lane * 4) = a0;
}

// ---------------- mma.sync helpers ----------------
__device__ __forceinline__ uint32_t smem_u32(const void* p) {
    uint32_t a;
    asm("{ .reg .u64 t; cvta.to.shared.u64 t, %1; cvt.u32.u64 %0, t; }"
        : "=r"(a) : "l"(p));
    return a;
}
__device__ __forceinline__ void ldsm4(uint32_t* r, uint32_t addr) {
    asm volatile("ldmatrix.sync.aligned.m8n8.x4.shared.b16 {%0,%1,%2,%3}, [%4];"
                 : "=r"(r[0]), "=r"(r[1]), "=r"(r[2]), "=r"(r[3]) : "r"(addr));
}
__device__ __forceinline__ void mma16816(float* d, const uint32_t* a,
                                         uint32_t b0, uint32_t b1) {
    asm volatile(
        "mma.sync.aligned.m16n8k16.row.col.f32.bf16.bf16.f32 "
        "{%0,%1,%2,%3}, {%4,%5,%6,%7}, {%8,%9}, {%0,%1,%2,%3};"
        : "+f"(d[0]), "+f"(d[1]), "+f"(d[2]), "+f"(d[3])
        : "r"(a[0]), "r"(a[1]), "r"(a[2]), "r"(a[3]), "r"(b0), "r"(b1));
}
__device__ __forceinline__ void cpa16(uint32_t dst, const void* src) {
    asm volatile("cp.async.ca.shared.global [%0], [%1], 16;"
                 :: "r"(dst), "l"(src) : "memory");
}
#define CPA_COMMIT() asm volatile("cp.async.commit_group;" ::: "memory")
#define CPA_WAIT0()  asm volatile("cp.async.wait_group 0;" ::: "memory")

// ---------------- tensor-core GEMM core (round-9 2D warp tiling, exact) ----
#define TSTRIDE 72   // elements; 144 bytes

template <int NP>
__device__ __forceinline__ void gemm_core(const float* const* Ap, const int* wp,
                                          float* __restrict__ Cout,
                                          const float* __restrict__ bias,
                                          int M, int m0)
{
    extern __shared__ __nv_bfloat16 smem[];
    __nv_bfloat16* Ah = smem;
    __nv_bfloat16* Al = Ah + 128 * TSTRIDE;
    __nv_bfloat16* Wh = Al + 128 * TSTRIDE;
    __nv_bfloat16* Wl = Wh + 128 * TSTRIDE;
    const uint32_t sAh = smem_u32(Ah);
    const uint32_t sAl = smem_u32(Al);
    const uint32_t sWh = smem_u32(Wh);
    const uint32_t sWl = smem_u32(Wl);

    int tid = threadIdx.x, w = tid >> 5, lane = tid & 31;
    int wm = w & 3;          // m-strip: rows [wm*32, wm*32+32)
    int wn = w >> 2;         // n-half:  cols [wn*64, wn*64+64)

    float acc[2][8][4];
    #pragma unroll
    for (int s = 0; s < 2; s++)
        #pragma unroll
        for (int i = 0; i < 8; i++)
            #pragma unroll
            for (int j = 0; j < 4; j++) acc[s][i][j] = 0.f;

    int a_row = lane & 15;
    int a_kh  = (lane >> 4) << 3;
    int b_n   = (lane & 7) + ((lane >> 4) << 3);
    int b_kh  = ((lane >> 3) & 1) << 3;

    #pragma unroll
    for (int p = 0; p < NP; p++) {
        const float* A = Ap[p];
        const __nv_bfloat16* WHsrc = g_Wsp[wp[p]][0];
        const __nv_bfloat16* WLsrc = g_Wsp[wp[p]][1];
        for (int c = 0; c < 2; c++) {
            __syncthreads();   // protect previous iteration's smem reads
            // ---- W chunk via cp.async (overlaps with A convert below)
            #pragma unroll
            for (int it = 0; it < 4; it++) {
                int q = tid + it * 256;
                int n = q >> 3;
                int j = q & 7;
                cpa16(sWh + (n * TSTRIDE + j * 8) * 2, WHsrc + n * 128 + c * 64 + j * 8);
                cpa16(sWl + (n * TSTRIDE + j * 8) * 2, WLsrc + n * 128 + c * 64 + j * 8);
            }
            CPA_COMMIT();
            // ---- load & split A chunk [128 m x 64 k]
            #pragma unroll
            for (int it = 0; it < 8; it++) {
                int q = tid + it * 256;
                int row = q >> 4;
                int k4  = (q & 15) << 2;
                int grow = m0 + row;
                float4 v = make_float4(0.f, 0.f, 0.f, 0.f);
                if (grow < M) v = *(const float4*)(A + (size_t)grow * DIMN + c * 64 + k4);
                __nv_bfloat16 h0 = __float2bfloat16_rn(v.x);
                __nv_bfloat16 h1 = __float2bfloat16_rn(v.y);
                __nv_bfloat16 h2 = __float2bfloat16_rn(v.z);
                __nv_bfloat16 h3 = __float2bfloat16_rn(v.w);
                ushort4 uh = make_ushort4(__bfloat16_as_ushort(h0), __bfloat16_as_ushort(h1),
                                          __bfloat16_as_ushort(h2), __bfloat16_as_ushort(h3));
                __nv_bfloat16 l0 = __float2bfloat16_rn(v.x - __bfloat162float(h0));
                __nv_bfloat16 l1 = __float2bfloat16_rn(v.y - __bfloat162float(h1));
                __nv_bfloat16 l2 = __float2bfloat16_rn(v.z - __bfloat162float(h2));
                __nv_bfloat16 l3 = __float2bfloat16_rn(v.w - __bfloat162float(h3));
                ushort4 ul = make_ushort4(__bfloat16_as_ushort(l0), __bfloat16_as_ushort(l1),
                                          __bfloat16_as_ushort(l2), __bfloat16_as_ushort(l3));
                *(ushort4*)(Ah + row * TSTRIDE + k4) = uh;
                *(ushort4*)(Al + row * TSTRIDE + k4) = ul;
            }
            CPA_WAIT0();
            __syncthreads();
            // ---- compute: warp (wm, wn) owns m32 x n64
            #pragma unroll
            for (int ks = 0; ks < 4; ks++) {
                uint32_t aH[2][4], aL[2][4];
                #pragma unroll
                for (int s = 0; s < 2; s++) {
                    uint32_t aoff = (uint32_t)((wm * 32 + s * 16 + a_row) * TSTRIDE
                                               + ks * 16 + a_kh) * 2;
                    ldsm4(aH[s], sAh + aoff);
                    ldsm4(aL[s], sAl + aoff);
                }
                #pragma unroll
                for (int nt = 0; nt < 4; nt++) {
                    uint32_t bH[4], bL[4];
                    uint32_t boff = (uint32_t)((wn * 64 + nt * 16 + b_n) * TSTRIDE
                                               + ks * 16 + b_kh) * 2;
                    ldsm4(bH, sWh + boff);
                    ldsm4(bL, sWl + boff);
                    #pragma unroll
                    for (int s = 0; s < 2; s++) {
                        mma16816(acc[s][nt * 2],     aH[s], bH[0], bH[1]);
                        mma16816(acc[s][nt * 2 + 1], aH[s], bH[2], bH[3]);
                        mma16816(acc[s][nt * 2],     aH[s], bL[0], bL[1]);
                        mma16816(acc[s][nt * 2 + 1], aH[s], bL[2], bL[3]);
                        mma16816(acc[s][nt * 2],     aL[s], bH[0], bH[1]);
                        mma16816(acc[s][nt * 2 + 1], aL[s], bH[2], bH[3]);
                    }
                }
            }
        }
    }

    // ---- epilogue
    int ncol = (lane & 3) * 2;
    #pragma unroll
    for (int s = 0; s < 2; s++) {
        int row0 = m0 + wm * 32 + s * 16 + (lane >> 2);
        int row1 = row0 + 8;
        #pragma unroll
        for (int t8 = 0; t8 < 8; t8++) {
            int n = wn * 64 + t8 * 8 + ncol;
            float2 bv = *(const float2*)(bias + n);
            if (row0 < M) {
                float2 o = make_float2(acc[s][t8][0] + bv.x, acc[s][t8][1] + bv.y);
                *(float2*)(Cout + (size_t)row0 * DIMN + n) = o;
            }
            if (row1 < M) {
                float2 o = make_float2(acc[s][t8][2] + bv.x, acc[s][t8][3] + bv.y);
                *(float2*)(Cout + (size_t)row1 * DIMN + n) = o;
            }
        }
    }
}

__global__ void __launch_bounds__(256, 2)
k_gemm_user(const float* __restrict__ xu, float* __restrict__ out, int NU) {
    const float* Ap[2] = {g_meanR, xu};
    const int wp[2] = {0, 1};
    gemm_core<2>(Ap, wp, out, g_biasU, NU, blockIdx.x * 128);
}

__global__ void __launch_bounds__(256, 2)
k_gemm_item(const float* __restrict__ xi, float* __restrict__ out, int NI) {
    const float* Ap[3] = {g_meanB, g_meanT, xi};
    const int wp[3] = {2, 3, 4};
    gemm_core<3>(Ap, wp, out, g_biasI, NI, blockIdx.x * 128);
}

// ---------------- launch: two-stream pipelined graph ----------------
extern "C" void kernel_launch(void* const* d_in, const int* in_sizes, int n_in,
                              void* d_out, int out_size) {
    const float* xu  = (const float*)d_in[0];
    const float* xi  = (const float*)d_in[1];
    const float* xt  = (const float*)d_in[2];
    const int*   eb  = (const int*)d_in[3];
    const int*   er  = (const int*)d_in[4];
    const int*   et  = (const int*)d_in[5];
    const float* WlB = (const float*)d_in[6];
    const float* WrB = (const float*)d_in[7];
    const float* bB  = (const float*)d_in[8];
    const float* WlR = (const float*)d_in[9];
    const float* WrR = (const float*)d_in[10];
    const float* bR  = (const float*)d_in[11];
    const float* WlT = (const float*)d_in[12];
    const float* WrT = (const float*)d_in[13];
    const float* bT  = (const float*)d_in[14];

    int NU = in_sizes[0] / DIMN;
    int NI = in_sizes[1] / DIMN;
    int NT = in_sizes[2] / DIMN;
    int EB = in_sizes[3] / 2;
    int ER = in_sizes[4] / 2;
    int ET = in_sizes[5] / 2;

    float* out_user = (float*)d_out;
    float* out_item = (float*)d_out + (size_t)NU * DIMN;

    float* dmB; cudaGetSymbolAddress((void**)&dmB, g_meanB);
    float* dmR; cudaGetSymbolAddress((void**)&dmR, g_meanR);
    float* dmT; cudaGetSymbolAddress((void**)&dmT, g_meanT);
    __half* xuh; cudaGetSymbolAddress((void**)&xuh, g_xuh);
    __half* xih; cudaGetSymbolAddress((void**)&xih, g_xih);
    __half* xth; cudaGetSymbolAddress((void**)&xth, g_xth);

    const int SMEM_BYTES = 4 * 128 * TSTRIDE * 2;   // 73728
    cudaFuncSetAttribute(k_gemm_user, cudaFuncAttributeMaxDynamicSharedMemorySize, SMEM_BYTES);
    cudaFuncSetAttribute(k_gemm_item, cudaFuncAttributeMaxDynamicSharedMemorySize, SMEM_BYTES);

    cudaStream_t s0 = 0;  // capture-origin (legacy) stream

    // init: zero counters + weight prep, then fork
    k_init<<<(3 * (NU_MAX + 1) + 255) / 256, 256, 0, s0>>>(WlR, WrR, WlB, WlT,
                                                           WrB, WrT, bR, bB, bT);
    cudaEventRecord(g_sk.ev0, s0);
    cudaStreamWaitEvent(g_sk.sA, g_sk.ev0, 0);
    cudaStreamWaitEvent(g_sk.sB, g_sk.ev0, 0);

    // ---- stream A: rel 1 (rev) -> out_user
    {
        int n = NI * DIMN;
        k_tohalf<<<(n / 4 + 255) / 256, 256, 0, g_sk.sA>>>(xi, xih, n);
    }
    k_hist1<<<(ER / 2 + 255) / 256, 256, 0, g_sk.sA>>>(er + ER, ER, 1);
    k_scan_pair<<<1, 1024, 0, g_sk.sA>>>(1, NU, 1, NU);
    k_fill1<<<(ER / 2 + 255) / 256, 256, 0, g_sk.sA>>>(er, ER, 1);
    k_agg1<<<(NU * 32 + 255) / 256, 256, 0, g_sk.sA>>>(xih, dmR, 1, NU);
    k_gemm_user<<<(NU + 127) / 128, 256, SMEM_BYTES, g_sk.sA>>>(xu, out_user, NU);
    cudaEventRecord(g_sk.evA, g_sk.sA);

    // ---- stream B: rels 0 (buys), 2 (tags) -> out_item
    {
        int n = NU * DIMN;
        k_tohalf<<<(n / 4 + 255) / 256, 256, 0, g_sk.sB>>>(xu, xuh, n);
        int m = NT * DIMN;
        k_tohalf<<<(m / 4 + 255) / 256, 256, 0, g_sk.sB>>>(xt, xth, m);
    }
    k_hist1<<<(EB / 2 + 255) / 256, 256, 0, g_sk.sB>>>(eb + EB, EB, 0);
    k_hist1<<<(ET / 2 + 255) / 256, 256, 0, g_sk.sB>>>(et + ET, ET, 2);
    k_scan_pair<<<2, 1024, 0, g_sk.sB>>>(0, NI, 2, NI);
    k_fill1<<<(EB / 2 + 255) / 256, 256, 0, g_sk.sB>>>(eb, EB, 0);
    k_fill1<<<(ET / 2 + 255) / 256, 256, 0, g_sk.sB>>>(et, ET, 2);
    k_agg1<<<(NI * 32 + 255) / 256, 256, 0, g_sk.sB>>>(xuh, dmB, 0, NI);
    k_agg1<<<(NI * 32 + 255) / 256, 256, 0, g_sk.sB>>>(xth, dmT, 2, NI);
    k_gemm_item<<<(NI + 127) / 128, 256, SMEM_BYTES, g_sk.sB>>>(xi, out_item, NI);
    cudaEventRecord(g_sk.evB, g_sk.sB);

    // ---- join back to origin stream
    cudaStreamWaitEvent(s0, g_sk.evA, 0);
    cudaStreamWaitEvent(s0, g_sk.evB, 0);
}

// round 14
// speedup vs baseline: 1.2836x; 1.1584x over previous
#include <cuda_runtime.h>
#include <cuda_bf16.h>
#include <cuda_fp16.h>
#include <cstddef>
#include <cstdint>

#define NU_MAX 100000
#define NI_MAX 100000
#define E_MAX  1000000
#define DIMN   128

// ---------------- scratch (static __device__, no allocation) ----------------
__device__ int   g_cnt[3][NU_MAX + 1];
__device__ int   g_off[3][NU_MAX + 1];
__device__ int   g_cur[3][NU_MAX];
__device__ int   g_adj[3][E_MAX];
__device__ int   g_bsum[3][1024];
__device__ float g_meanB[(size_t)NI_MAX * DIMN];
__device__ float g_meanR[(size_t)NU_MAX * DIMN];
__device__ float g_meanT[(size_t)NI_MAX * DIMN];

// fp16 copies of node features for low-traffic gathering
__device__ __align__(16) __half g_xuh[(size_t)NU_MAX * DIMN];
__device__ __align__(16) __half g_xih[(size_t)NI_MAX * DIMN];
__device__ __align__(16) __half g_xth[(size_t)NU_MAX * DIMN];  // sized safe

// split + transposed weights: [panel][half hi/lo][n*128+k] bf16
__device__ __align__(16) __nv_bfloat16 g_Wsp[5][2][DIMN * DIMN];
__device__ __align__(16) float g_biasU[DIMN];
__device__ __align__(16) float g_biasI[DIMN];

// ---------------- host-side streams/events (created once, before capture) ----
namespace {
struct StreamKit {
    cudaStream_t sA, sB;
    cudaEvent_t ev0, evA, evB;
    StreamKit() {
        cudaStreamCreateWithFlags(&sA, cudaStreamNonBlocking);
        cudaStreamCreateWithFlags(&sB, cudaStreamNonBlocking);
        cudaEventCreateWithFlags(&ev0, cudaEventDisableTiming);
        cudaEventCreateWithFlags(&evA, cudaEventDisableTiming);
        cudaEventCreateWithFlags(&evB, cudaEventDisableTiming);
    }
};
StreamKit g_sk;
}

// ---------------- init: zero counters + weight prep (merged) ----------------
__global__ void k_init(const float* __restrict__ WlR, const float* __restrict__ WrR,
                       const float* __restrict__ WlB, const float* __restrict__ WlT,
                       const float* __restrict__ WrB, const float* __restrict__ WrT,
                       const float* __restrict__ bR, const float* __restrict__ bB,
                       const float* __restrict__ bT) {
    int i = blockIdx.x * blockDim.x + threadIdx.x;
    const int total = 3 * (NU_MAX + 1);
    if (i < total) ((int*)g_cnt)[i] = 0;
    if (i < 5 * 16384) {
        int panel = i >> 14;
        int e = i & 16383;
        int k = e >> 7;
        int n = e & 127;
        float v;
        switch (panel) {
            case 0:  v = WlR[k * 128 + n]; break;
            case 1:  v = WrR[k * 128 + n]; break;
            case 2:  v = 0.5f * WlB[k * 128 + n]; break;
            case 3:  v = 0.5f * WlT[k * 128 + n]; break;
            default: v = 0.5f * (WrB[k * 128 + n] + WrT[k * 128 + n]);
        }
        __nv_bfloat16 h = __float2bfloat16_rn(v);
        __nv_bfloat16 l = __float2bfloat16_rn(v - __bfloat162float(h));
        g_Wsp[panel][0][n * 128 + k] = h;
        g_Wsp[panel][1][n * 128 + k] = l;
    }
    if (i < DIMN) {
        g_biasU[i] = bR[i];
        g_biasI[i] = 0.5f * (bB[i] + bT[i]);
    }
}

// ---------------- fp32 -> fp16 feature conversion ----------------
__global__ void k_tohalf(const float* __restrict__ x, __half* __restrict__ xh, int n) {
    int i = (blockIdx.x * blockDim.x + threadIdx.x) * 4;
    if (i < n) {
        float4 v = *(const float4*)(x + i);
        __half2 a = __floats2half2_rn(v.x, v.y);
        __half2 b = __floats2half2_rn(v.z, v.w);
        uint2 u;
        u.x = *reinterpret_cast<uint32_t*>(&a);
        u.y = *reinterpret_cast<uint32_t*>(&b);
        *(uint2*)(xh + i) = u;
    }
}

// ---------------- CSR build: per-relation kernels (2 edges/thread) ----------
__global__ void k_hist1(const int* __restrict__ dst, int E, int rel) {
    int t = blockIdx.x * blockDim.x + threadIdx.x;
    #pragma unroll
    for (int j = 0; j < 2; j++) {
        int e = t * 2 + j;
        if (e < E) atomicAdd(&g_cnt[rel][dst[e]], 1);
    }
}

// ---------------- parallel 3-pass exclusive scan ----------------
// pass 1: per-block (1024-wide) exclusive scan of g_cnt; block totals -> g_bsum
__global__ void k_scan1(int rel, int n) {
    int tid = threadIdx.x;
    int i = blockIdx.x * 1024 + tid;
    int lane = tid & 31, wid = tid >> 5;
    __shared__ int wsum[32];
    int v = (i < n) ? g_cnt[rel][i] : 0;
    int s = v;
    #pragma unroll
    for (int d = 1; d < 32; d <<= 1) {
        int t = __shfl_up_sync(0xFFFFFFFFu, s, d);
        if (lane >= d) s += t;
    }
    if (lane == 31) wsum[wid] = s;
    __syncthreads();
    if (wid == 0) {
        int w = wsum[lane];
        #pragma unroll
        for (int d = 1; d < 32; d <<= 1) {
            int t = __shfl_up_sync(0xFFFFFFFFu, w, d);
            if (lane >= d) w += t;
        }
        wsum[lane] = w;
    }
    __syncthreads();
    int woff = (wid > 0) ? wsum[wid - 1] : 0;
    if (i < n) g_off[rel][i] = woff + s - v;   // block-local exclusive
    if (tid == 1023) g_bsum[rel][blockIdx.x] = woff + s;  // block total
}

// pass 2: single block — exclusive scan of block totals; writes g_off[n]=grand total
__global__ void k_scan2(int r0, int nblk0, int n0, int r1, int nblk1, int n1) {
    int rel  = (blockIdx.x == 0) ? r0 : r1;
    int nblk = (blockIdx.x == 0) ? nblk0 : nblk1;
    int n    = (blockIdx.x == 0) ? n0 : n1;
    int tid = threadIdx.x;
    int lane = tid & 31, wid = tid >> 5;
    __shared__ int wsum[32];
    int v = (tid < nblk) ? g_bsum[rel][tid] : 0;
    int s = v;
    #pragma unroll
    for (int d = 1; d < 32; d <<= 1) {
        int t = __shfl_up_sync(0xFFFFFFFFu, s, d);
        if (lane >= d) s += t;
    }
    if (lane == 31) wsum[wid] = s;
    __syncthreads();
    if (wid == 0) {
        int w = wsum[lane];
        #pragma unroll
        for (int d = 1; d < 32; d <<= 1) {
            int t = __shfl_up_sync(0xFFFFFFFFu, w, d);
            if (lane >= d) w += t;
        }
        wsum[lane] = w;
    }
    __syncthreads();
    int woff = (wid > 0) ? wsum[wid - 1] : 0;
    if (tid < nblk) g_bsum[rel][tid] = woff + s - v;   // exclusive
    if (tid == 1023) g_off[rel][n] = woff + s;          // grand total
}

// pass 3: add block offsets; produce final g_off/g_cur
__global__ void k_scan3(int rel, int n) {
    int i = blockIdx.x * 256 + threadIdx.x;
    if (i < n) {
        int off = g_off[rel][i] + g_bsum[rel][i >> 10];
        g_off[rel][i] = off;
        g_cur[rel][i] = off;
    }
}

__global__ void k_fill1(const int* __restrict__ ei, int E, int rel) {
    int t = blockIdx.x * blockDim.x + threadIdx.x;
    #pragma unroll
    for (int j = 0; j < 2; j++) {
        int e = t * 2 + j;
        if (e < E) {
            int d = ei[E + e];
            int s = ei[e];
            int p = atomicAdd(&g_cur[rel][d], 1);
            g_adj[rel][p] = s;
        }
    }
}

// ---------------- mean aggregation: fp16 gather, fp32 accumulate ------------
__global__ void k_agg1(const __half* __restrict__ xs, float* __restrict__ mean,
                       int rel, int n_dst) {
    int node = (blockIdx.x * blockDim.x + threadIdx.x) >> 5;
    int lane = threadIdx.x & 31;
    if (node >= n_dst) return;

    const int* __restrict__ adj = g_adj[rel];
    int s0 = g_off[rel][node], s1 = g_off[rel][node + 1];
    float4 a0 = make_float4(0.f, 0.f, 0.f, 0.f);
    float4 a1 = make_float4(0.f, 0.f, 0.f, 0.f);
    float4 a2 = make_float4(0.f, 0.f, 0.f, 0.f);
    float4 a3 = make_float4(0.f, 0.f, 0.f, 0.f);
    int e = s0;
    for (; e + 3 < s1; e += 4) {
        int i0 = __ldg(&adj[e]);
        int i1 = __ldg(&adj[e + 1]);
        int i2 = __ldg(&adj[e + 2]);
        int i3 = __ldg(&adj[e + 3]);
        uint2 u0 = *(const uint2*)(xs + (size_t)i0 * DIMN + lane * 4);
        uint2 u1 = *(const uint2*)(xs + (size_t)i1 * DIMN + lane * 4);
        uint2 u2 = *(const uint2*)(xs + (size_t)i2 * DIMN + lane * 4);
        uint2 u3 = *(const uint2*)(xs + (size_t)i3 * DIMN + lane * 4);
        float2 p, q;
        p = __half22float2(*reinterpret_cast<__half2*>(&u0.x));
        q = __half22float2(*reinterpret_cast<__half2*>(&u0.y));
        a0.x += p.x; a0.y += p.y; a0.z += q.x; a0.w += q.y;
        p = __half22float2(*reinterpret_cast<__half2*>(&u1.x));
        q = __half22float2(*reinterpret_cast<__half2*>(&u1.y));
        a1.x += p.x; a1.y += p.y; a1.z += q.x; a1.w += q.y;
        p = __half22float2(*reinterpret_cast<__half2*>(&u2.x));
        q = __half22float2(*reinterpret_cast<__half2*>(&u2.y));
        a2.x += p.x; a2.y += p.y; a2.z += q.x; a2.w += q.y;
        p = __half22float2(*reinterpret_cast<__half2*>(&u3.x));
        q = __half22float2(*reinterpret_cast<__half2*>(&u3.y));
        a3.x += p.x; a3.y += p.y; a3.z += q.x; a3.w += q.y;
    }
    for (; e < s1; e++) {
        int i0 = __ldg(&adj[e]);
        uint2 u0 = *(const uint2*)(xs + (size_t)i0 * DIMN + lane * 4);
        float2 p = __half22float2(*reinterpret_cast<__half2*>(&u0.x));
        float2 q = __half22float2(*reinterpret_cast<__half2*>(&u0.y));
        a0.x += p.x; a0.y += p.y; a0.z += q.x; a0.w += q.y;
    }
    a0.x += a1.x + a2.x + a3.x;
    a0.y += a1.y + a2.y + a3.y;
    a0.z += a1.z + a2.z + a3.z;
    a0.w += a1.w + a2.w + a3.w;
    int deg = s1 - s0;
    float inv = 1.0f / (float)(deg > 0 ? deg : 1);
    a0.x *= inv; a0.y *= inv; a0.z *= inv; a0.w *= inv;
    *(float4*)(mean + (size_t)node * DIMN + lane * 4) = a0;
}

// ---------------- mma.sync helpers ----------------
__device__ __forceinline__ uint32_t smem_u32(const void* p) {
    uint32_t a;
    asm("{ .reg .u64 t; cvta.to.shared.u64 t, %1; cvt.u32.u64 %0, t; }"
        : "=r"(a) : "l"(p));
    return a;
}
__device__ __forceinline__ void ldsm4(uint32_t* r, uint32_t addr) {
    asm volatile("ldmatrix.sync.aligned.m8n8.x4.shared.b16 {%0,%1,%2,%3}, [%4];"
                 : "=r"(r[0]), "=r"(r[1]), "=r"(r[2]), "=r"(r[3]) : "r"(addr));
}
__device__ __forceinline__ void mma16816(float* d, const uint32_t* a,
                                         uint32_t b0, uint32_t b1) {
    asm volatile(
        "mma.sync.aligned.m16n8k16.row.col.f32.bf16.bf16.f32 "
        "{%0,%1,%2,%3}, {%4,%5,%6,%7}, {%8,%9}, {%0,%1,%2,%3};"
        : "+f"(d[0]), "+f"(d[1]), "+f"(d[2]), "+f"(d[3])
        : "r"(a[0]), "r"(a[1]), "r"(a[2]), "r"(a[3]), "r"(b0), "r"(b1));
}
__device__ __forceinline__ void cpa16(uint32_t dst, const void* src) {
    asm volatile("cp.async.ca.shared.global [%0], [%1], 16;"
                 :: "r"(dst), "l"(src) : "memory");
}
#define CPA_COMMIT() asm volatile("cp.async.commit_group;" ::: "memory")
#define CPA_WAIT0()  asm volatile("cp.async.wait_group 0;" ::: "memory")

// ---------------- tensor-core GEMM core (round-9 2D warp tiling, exact) ----
#define TSTRIDE 72   // elements; 144 bytes

template <int NP>
__device__ __forceinline__ void gemm_core(const float* const* Ap, const int* wp,
                                          float* __restrict__ Cout,
                                          const float* __restrict__ bias,
                                          int M, int m0)
{
    extern __shared__ __nv_bfloat16 smem[];
    __nv_bfloat16* Ah = smem;
    __nv_bfloat16* Al = Ah + 128 * TSTRIDE;
    __nv_bfloat16* Wh = Al + 128 * TSTRIDE;
    __nv_bfloat16* Wl = Wh + 128 * TSTRIDE;
    const uint32_t sAh = smem_u32(Ah);
    const uint32_t sAl = smem_u32(Al);
    const uint32_t sWh = smem_u32(Wh);
    const uint32_t sWl = smem_u32(Wl);

    int tid = threadIdx.x, w = tid >> 5, lane = tid & 31;
    int wm = w & 3;          // m-strip: rows [wm*32, wm*32+32)
    int wn = w >> 2;         // n-half:  cols [wn*64, wn*64+64)

    float acc[2][8][4];
    #pragma unroll
    for (int s = 0; s < 2; s++)
        #pragma unroll
        for (int i = 0; i < 8; i++)
            #pragma unroll
            for (int j = 0; j < 4; j++) acc[s][i][j] = 0.f;

    int a_row = lane & 15;
    int a_kh  = (lane >> 4) << 3;
    int b_n   = (lane & 7) + ((lane >> 4) << 3);
    int b_kh  = ((lane >> 3) & 1) << 3;

    #pragma unroll
    for (int p = 0; p < NP; p++) {
        const float* A = Ap[p];
        const __nv_bfloat16* WHsrc = g_Wsp[wp[p]][0];
        const __nv_bfloat16* WLsrc = g_Wsp[wp[p]][1];
        for (int c = 0; c < 2; c++) {
            __syncthreads();   // protect previous iteration's smem reads
            // ---- W chunk via cp.async (overlaps with A convert below)
            #pragma unroll
            for (int it = 0; it < 4; it++) {
                int q = tid + it * 256;
                int n = q >> 3;
                int j = q & 7;
                cpa16(sWh + (n * TSTRIDE + j * 8) * 2, WHsrc + n * 128 + c * 64 + j * 8);
                cpa16(sWl + (n * TSTRIDE + j * 8) * 2, WLsrc + n * 128 + c * 64 + j * 8);
            }
            CPA_COMMIT();
            // ---- load & split A chunk [128 m x 64 k]
            #pragma unroll
            for (int it = 0; it < 8; it++) {
                int q = tid + it * 256;
                int row = q >> 4;
                int k4  = (q & 15) << 2;
                int grow = m0 + row;
                float4 v = make_float4(0.f, 0.f, 0.f, 0.f);
                if (grow < M) v = *(const float4*)(A + (size_t)grow * DIMN + c * 64 + k4);
                __nv_bfloat16 h0 = __float2bfloat16_rn(v.x);
                __nv_bfloat16 h1 = __float2bfloat16_rn(v.y);
                __nv_bfloat16 h2 = __float2bfloat16_rn(v.z);
                __nv_bfloat16 h3 = __float2bfloat16_rn(v.w);
                ushort4 uh = make_ushort4(__bfloat16_as_ushort(h0), __bfloat16_as_ushort(h1),
                                          __bfloat16_as_ushort(h2), __bfloat16_as_ushort(h3));
                __nv_bfloat16 l0 = __float2bfloat16_rn(v.x - __bfloat162float(h0));
                __nv_bfloat16 l1 = __float2bfloat16_rn(v.y - __bfloat162float(h1));
                __nv_bfloat16 l2 = __float2bfloat16_rn(v.z - __bfloat162float(h2));
                __nv_bfloat16 l3 = __float2bfloat16_rn(v.w - __bfloat162float(h3));
                ushort4 ul = make_ushort4(__bfloat16_as_ushort(l0), __bfloat16_as_ushort(l1),
                                          __bfloat16_as_ushort(l2), __bfloat16_as_ushort(l3));
                *(ushort4*)(Ah + row * TSTRIDE + k4) = uh;
                *(ushort4*)(Al + row * TSTRIDE + k4) = ul;
            }
            CPA_WAIT0();
            __syncthreads();
            // ---- compute: warp (wm, wn) owns m32 x n64
            #pragma unroll
            for (int ks = 0; ks < 4; ks++) {
                uint32_t aH[2][4], aL[2][4];
                #pragma unroll
                for (int s = 0; s < 2; s++) {
                    uint32_t aoff = (uint32_t)((wm * 32 + s * 16 + a_row) * TSTRIDE
                                               + ks * 16 + a_kh) * 2;
                    ldsm4(aH[s], sAh + aoff);
                    ldsm4(aL[s], sAl + aoff);
                }
                #pragma unroll
                for (int nt = 0; nt < 4; nt++) {
                    uint32_t bH[4], bL[4];
                    uint32_t boff = (uint32_t)((wn * 64 + nt * 16 + b_n) * TSTRIDE
                                               + ks * 16 + b_kh) * 2;
                    ldsm4(bH, sWh + boff);
                    ldsm4(bL, sWl + boff);
                    #pragma unroll
                    for (int s = 0; s < 2; s++) {
                        mma16816(acc[s][nt * 2],     aH[s], bH[0], bH[1]);
                        mma16816(acc[s][nt * 2 + 1], aH[s], bH[2], bH[3]);
                        mma16816(acc[s][nt * 2],     aH[s], bL[0], bL[1]);
                        mma16816(acc[s][nt * 2 + 1], aH[s], bL[2], bL[3]);
                        mma16816(acc[s][nt * 2],     aL[s], bH[0], bH[1]);
                        mma16816(acc[s][nt * 2 + 1], aL[s], bH[2], bH[3]);
                    }
                }
            }
        }
    }

    // ---- epilogue
    int ncol = (lane & 3) * 2;
    #pragma unroll
    for (int s = 0; s < 2; s++) {
        int row0 = m0 + wm * 32 + s * 16 + (lane >> 2);
        int row1 = row0 + 8;
        #pragma unroll
        for (int t8 = 0; t8 < 8; t8++) {
            int n = wn * 64 + t8 * 8 + ncol;
            float2 bv = *(const float2*)(bias + n);
            if (row0 < M) {
                float2 o = make_float2(acc[s][t8][0] + bv.x, acc[s][t8][1] + bv.y);
                *(float2*)(Cout + (size_t)row0 * DIMN + n) = o;
            }
            if (row1 < M) {
                float2 o = make_float2(acc[s][t8][2] + bv.x, acc[s][t8][3] + bv.y);
                *(float2*)(Cout + (size_t)row1 * DIMN + n) = o;
            }
        }
    }
}

__global__ void __launch_bounds__(256, 2)
k_gemm_user(const float* __restrict__ xu, float* __restrict__ out, int NU) {
    const float* Ap[2] = {g_meanR, xu};
    const int wp[2] = {0, 1};
    gemm_core<2>(Ap, wp, out, g_biasU, NU, blockIdx.x * 128);
}

__global__ void __launch_bounds__(256, 2)
k_gemm_item(const float* __restrict__ xi, float* __restrict__ out, int NI) {
    const float* Ap[3] = {g_meanB, g_meanT, xi};
    const int wp[3] = {2, 3, 4};
    gemm_core<3>(Ap, wp, out, g_biasI, NI, blockIdx.x * 128);
}

// ---------------- launch: two-stream pipelined graph ----------------
extern "C" void kernel_launch(void* const* d_in, const int* in_sizes, int n_in,
                              void* d_out, int out_size) {
    const float* xu  = (const float*)d_in[0];
    const float* xi  = (const float*)d_in[1];
    const float* xt  = (const float*)d_in[2];
    const int*   eb  = (const int*)d_in[3];
    const int*   er  = (const int*)d_in[4];
    const int*   et  = (const int*)d_in[5];
    const float* WlB = (const float*)d_in[6];
    const float* WrB = (const float*)d_in[7];
    const float* bB  = (const float*)d_in[8];
    const float* WlR = (const float*)d_in[9];
    const float* WrR = (const float*)d_in[10];
    const float* bR  = (const float*)d_in[11];
    const float* WlT = (const float*)d_in[12];
    const float* WrT = (const float*)d_in[13];
    const float* bT  = (const float*)d_in[14];

    int NU = in_sizes[0] / DIMN;
    int NI = in_sizes[1] / DIMN;
    int NT = in_sizes[2] / DIMN;
    int EB = in_sizes[3] / 2;
    int ER = in_sizes[4] / 2;
    int ET = in_sizes[5] / 2;

    float* out_user = (float*)d_out;
    float* out_item = (float*)d_out + (size_t)NU * DIMN;

    float* dmB; cudaGetSymbolAddress((void**)&dmB, g_meanB);
    float* dmR; cudaGetSymbolAddress((void**)&dmR, g_meanR);
    float* dmT; cudaGetSymbolAddress((void**)&dmT, g_meanT);
    __half* xuh; cudaGetSymbolAddress((void**)&xuh, g_xuh);
    __half* xih; cudaGetSymbolAddress((void**)&xih, g_xih);
    __half* xth; cudaGetSymbolAddress((void**)&xth, g_xth);

    const int SMEM_BYTES = 4 * 128 * TSTRIDE * 2;   // 73728
    cudaFuncSetAttribute(k_gemm_user, cudaFuncAttributeMaxDynamicSharedMemorySize, SMEM_BYTES);
    cudaFuncSetAttribute(k_gemm_item, cudaFuncAttributeMaxDynamicSharedMemorySize, SMEM_BYTES);

    int nblkU = (NU + 1023) / 1024;
    int nblkI = (NI + 1023) / 1024;

    cudaStream_t s0 = 0;  // capture-origin (legacy) stream

    // init: zero counters + weight prep, then fork
    k_init<<<(3 * (NU_MAX + 1) + 255) / 256, 256, 0, s0>>>(WlR, WrR, WlB, WlT,
                                                           WrB, WrT, bR, bB, bT);
    cudaEventRecord(g_sk.ev0, s0);
    cudaStreamWaitEvent(g_sk.sA, g_sk.ev0, 0);
    cudaStreamWaitEvent(g_sk.sB, g_sk.ev0, 0);

    // ---- stream A: rel 1 (rev) -> out_user
    {
        int n = NI * DIMN;
        k_tohalf<<<(n / 4 + 255) / 256, 256, 0, g_sk.sA>>>(xi, xih, n);
    }
    k_hist1<<<(ER / 2 + 255) / 256, 256, 0, g_sk.sA>>>(er + ER, ER, 1);
    k_scan1<<<nblkU, 1024, 0, g_sk.sA>>>(1, NU);
    k_scan2<<<1, 1024, 0, g_sk.sA>>>(1, nblkU, NU, 1, nblkU, NU);
    k_scan3<<<(NU + 255) / 256, 256, 0, g_sk.sA>>>(1, NU);
    k_fill1<<<(ER / 2 + 255) / 256, 256, 0, g_sk.sA>>>(er, ER, 1);
    k_agg1<<<(NU * 32 + 255) / 256, 256, 0, g_sk.sA>>>(xih, dmR, 1, NU);
    k_gemm_user<<<(NU + 127) / 128, 256, SMEM_BYTES, g_sk.sA>>>(xu, out_user, NU);
    cudaEventRecord(g_sk.evA, g_sk.sA);

    // ---- stream B: rels 0 (buys), 2 (tags) -> out_item
    {
        int n = NU * DIMN;
        k_tohalf<<<(n / 4 + 255) / 256, 256, 0, g_sk.sB>>>(xu, xuh, n);
        int m = NT * DIMN;
        k_tohalf<<<(m / 4 + 255) / 256, 256, 0, g_sk.sB>>>(xt, xth, m);
    }
    k_hist1<<<(EB / 2 + 255) / 256, 256, 0, g_sk.sB>>>(eb + EB, EB, 0);
    k_hist1<<<(ET / 2 + 255) / 256, 256, 0, g_sk.sB>>>(et + ET, ET, 2);
    k_scan1<<<nblkI, 1024, 0, g_sk.sB>>>(0, NI);
    k_scan1<<<nblkI, 1024, 0, g_sk.sB>>>(2, NI);
    k_scan2<<<2, 1024, 0, g_sk.sB>>>(0, nblkI, NI, 2, nblkI, NI);
    k_scan3<<<(NI + 255) / 256, 256, 0, g_sk.sB>>>(0, NI);
    k_scan3<<<(NI + 255) / 256, 256, 0, g_sk.sB>>>(2, NI);
    k_fill1<<<(EB / 2 + 255) / 256, 256, 0, g_sk.sB>>>(eb, EB, 0);
    k_fill1<<<(ET / 2 + 255) / 256, 256, 0, g_sk.sB>>>(et, ET, 2);
    k_agg1<<<(NI * 32 + 255) / 256, 256, 0, g_sk.sB>>>(xuh, dmB, 0, NI);
    k_agg1<<<(NI * 32 + 255) / 256, 256, 0, g_sk.sB>>>(xth, dmT, 2, NI);
    k_gemm_item<<<(NI + 127) / 128, 256, SMEM_BYTES, g_sk.sB>>>(xi, out_item, NI);
    cudaEventRecord(g_sk.evB, g_sk.sB);

    // ---- join back to origin stream
    cudaStreamWaitEvent(s0, g_sk.evA, 0);
    cudaStreamWaitEvent(s0, g_sk.evB, 0);
}

// round 16
// speedup vs baseline: 1.2880x; 1.0035x over previous
#include <cuda_runtime.h>
#include <cuda_bf16.h>
#include <cuda_fp16.h>
#include <cstddef>
#include <cstdint>

#define NU_MAX 100000
#define NI_MAX 100000
#define E_MAX  1000000
#define DIMN   128

// ---------------- scratch (static __device__, no allocation) ----------------
__device__ int   g_cnt[3][NU_MAX + 1];
__device__ int   g_off[3][NU_MAX + 1];
__device__ int   g_cur[3][NU_MAX];
__device__ int   g_adj[3][E_MAX];
__device__ int   g_bsum[3][1024];

// fp16 means (fp32-accumulated, rounded once)
__device__ __align__(16) __half g_meanBh[(size_t)NI_MAX * DIMN];
__device__ __align__(16) __half g_meanRh[(size_t)NU_MAX * DIMN];
__device__ __align__(16) __half g_meanTh[(size_t)NI_MAX * DIMN];

// fp16 copies of node features
__device__ __align__(16) __half g_xuh[(size_t)NU_MAX * DIMN];
__device__ __align__(16) __half g_xih[(size_t)NI_MAX * DIMN];
__device__ __align__(16) __half g_xth[(size_t)NU_MAX * DIMN];  // sized safe

// split + transposed weights: [panel][half hi/lo][n*128+k] bf16
__device__ __align__(16) __nv_bfloat16 g_Wsp[5][2][DIMN * DIMN];
__device__ __align__(16) float g_biasU[DIMN];
__device__ __align__(16) float g_biasI[DIMN];

// ---------------- host-side streams/events (created once, before capture) ----
namespace {
struct StreamKit {
    cudaStream_t sA, sB;
    cudaEvent_t ev0, evA, evB, evCA, evCB;
    StreamKit() {
        cudaStreamCreateWithFlags(&sA, cudaStreamNonBlocking);
        cudaStreamCreateWithFlags(&sB, cudaStreamNonBlocking);
        cudaEventCreateWithFlags(&ev0, cudaEventDisableTiming);
        cudaEventCreateWithFlags(&evA, cudaEventDisableTiming);
        cudaEventCreateWithFlags(&evB, cudaEventDisableTiming);
        cudaEventCreateWithFlags(&evCA, cudaEventDisableTiming);
        cudaEventCreateWithFlags(&evCB, cudaEventDisableTiming);
    }
};
StreamKit g_sk;
}

// ---------------- init: zero counters + weight prep (merged) ----------------
__global__ void k_init(const float* __restrict__ WlR, const float* __restrict__ WrR,
                       const float* __restrict__ WlB, const float* __restrict__ WlT,
                       const float* __restrict__ WrB, const float* __restrict__ WrT,
                       const float* __restrict__ bR, const float* __restrict__ bB,
                       const float* __restrict__ bT) {
    int i = blockIdx.x * blockDim.x + threadIdx.x;
    const int total = 3 * (NU_MAX + 1);
    if (i < total) ((int*)g_cnt)[i] = 0;
    if (i < 5 * 16384) {
        int panel = i >> 14;
        int e = i & 16383;
        int k = e >> 7;
        int n = e & 127;
        float v;
        switch (panel) {
            case 0:  v = WlR[k * 128 + n]; break;
            case 1:  v = WrR[k * 128 + n]; break;
            case 2:  v = 0.5f * WlB[k * 128 + n]; break;
            case 3:  v = 0.5f * WlT[k * 128 + n]; break;
            default: v = 0.5f * (WrB[k * 128 + n] + WrT[k * 128 + n]);
        }
        __nv_bfloat16 h = __float2bfloat16_rn(v);
        __nv_bfloat16 l = __float2bfloat16_rn(v - __bfloat162float(h));
        g_Wsp[panel][0][n * 128 + k] = h;
        g_Wsp[panel][1][n * 128 + k] = l;
    }
    if (i < DIMN) {
        g_biasU[i] = bR[i];
        g_biasI[i] = 0.5f * (bB[i] + bT[i]);
    }
}

// ---------------- fp32 -> fp16 feature conversion ----------------
__global__ void k_tohalf(const float* __restrict__ x, __half* __restrict__ xh, int n) {
    int i = (blockIdx.x * blockDim.x + threadIdx.x) * 4;
    if (i < n) {
        float4 v = *(const float4*)(x + i);
        __half2 a = __floats2half2_rn(v.x, v.y);
        __half2 b = __floats2half2_rn(v.z, v.w);
        uint2 u;
        u.x = *reinterpret_cast<uint32_t*>(&a);
        u.y = *reinterpret_cast<uint32_t*>(&b);
        *(uint2*)(xh + i) = u;
    }
}

// ---------------- CSR build: per-relation kernels (2 edges/thread) ----------
__global__ void k_hist1(const int* __restrict__ dst, int E, int rel) {
    int t = blockIdx.x * blockDim.x + threadIdx.x;
    #pragma unroll
    for (int j = 0; j < 2; j++) {
        int e = t * 2 + j;
        if (e < E) atomicAdd(&g_cnt[rel][dst[e]], 1);
    }
}

// ---------------- parallel 3-pass exclusive scan ----------------
__global__ void k_scan1(int rel, int n) {
    int tid = threadIdx.x;
    int i = blockIdx.x * 1024 + tid;
    int lane = tid & 31, wid = tid >> 5;
    __shared__ int wsum[32];
    int v = (i < n) ? g_cnt[rel][i] : 0;
    int s = v;
    #pragma unroll
    for (int d = 1; d < 32; d <<= 1) {
        int t = __shfl_up_sync(0xFFFFFFFFu, s, d);
        if (lane >= d) s += t;
    }
    if (lane == 31) wsum[wid] = s;
    __syncthreads();
    if (wid == 0) {
        int w = wsum[lane];
        #pragma unroll
        for (int d = 1; d < 32; d <<= 1) {
            int t = __shfl_up_sync(0xFFFFFFFFu, w, d);
            if (lane >= d) w += t;
        }
        wsum[lane] = w;
    }
    __syncthreads();
    int woff = (wid > 0) ? wsum[wid - 1] : 0;
    if (i < n) g_off[rel][i] = woff + s - v;
    if (tid == 1023) g_bsum[rel][blockIdx.x] = woff + s;
}

__global__ void k_scan2(int r0, int nblk0, int n0, int r1, int nblk1, int n1) {
    int rel  = (blockIdx.x == 0) ? r0 : r1;
    int nblk = (blockIdx.x == 0) ? nblk0 : nblk1;
    int n    = (blockIdx.x == 0) ? n0 : n1;
    int tid = threadIdx.x;
    int lane = tid & 31, wid = tid >> 5;
    __shared__ int wsum[32];
    int v = (tid < nblk) ? g_bsum[rel][tid] : 0;
    int s = v;
    #pragma unroll
    for (int d = 1; d < 32; d <<= 1) {
        int t = __shfl_up_sync(0xFFFFFFFFu, s, d);
        if (lane >= d) s += t;
    }
    if (lane == 31) wsum[wid] = s;
    __syncthreads();
    if (wid == 0) {
        int w = wsum[lane];
        #pragma unroll
        for (int d = 1; d < 32; d <<= 1) {
            int t = __shfl_up_sync(0xFFFFFFFFu, w, d);
            if (lane >= d) w += t;
        }
        wsum[lane] = w;
    }
    __syncthreads();
    int woff = (wid > 0) ? wsum[wid - 1] : 0;
    if (tid < nblk) g_bsum[rel][tid] = woff + s - v;
    if (tid == 1023) g_off[rel][n] = woff + s;
}

__global__ void k_scan3(int rel, int n) {
    int i = blockIdx.x * 256 + threadIdx.x;
    if (i < n) {
        int off = g_off[rel][i] + g_bsum[rel][i >> 10];
        g_off[rel][i] = off;
        g_cur[rel][i] = off;
    }
}

__global__ void k_fill1(const int* __restrict__ ei, int E, int rel) {
    int t = blockIdx.x * blockDim.x + threadIdx.x;
    #pragma unroll
    for (int j = 0; j < 2; j++) {
        int e = t * 2 + j;
        if (e < E) {
            int d = ei[E + e];
            int s = ei[e];
            int p = atomicAdd(&g_cur[rel][d], 1);
            g_adj[rel][p] = s;
        }
    }
}

// ---------------- mean aggregation: fp16 gather, fp32 accumulate, fp16 store
__global__ void k_agg1(const __half* __restrict__ xs, __half* __restrict__ mean,
                       int rel, int n_dst) {
    int node = (blockIdx.x * blockDim.x + threadIdx.x) >> 5;
    int lane = threadIdx.x & 31;
    if (node >= n_dst) return;

    const int* __restrict__ adj = g_adj[rel];
    int s0 = g_off[rel][node], s1 = g_off[rel][node + 1];
    float4 a0 = make_float4(0.f, 0.f, 0.f, 0.f);
    float4 a1 = make_float4(0.f, 0.f, 0.f, 0.f);
    float4 a2 = make_float4(0.f, 0.f, 0.f, 0.f);
    float4 a3 = make_float4(0.f, 0.f, 0.f, 0.f);
    int e = s0;
    for (; e + 3 < s1; e += 4) {
        int i0 = __ldg(&adj[e]);
        int i1 = __ldg(&adj[e + 1]);
        int i2 = __ldg(&adj[e + 2]);
        int i3 = __ldg(&adj[e + 3]);
        uint2 u0 = *(const uint2*)(xs + (size_t)i0 * DIMN + lane * 4);
        uint2 u1 = *(const uint2*)(xs + (size_t)i1 * DIMN + lane * 4);
        uint2 u2 = *(const uint2*)(xs + (size_t)i2 * DIMN + lane * 4);
        uint2 u3 = *(const uint2*)(xs + (size_t)i3 * DIMN + lane * 4);
        float2 p, q;
        p = __half22float2(*reinterpret_cast<__half2*>(&u0.x));
        q = __half22float2(*reinterpret_cast<__half2*>(&u0.y));
        a0.x += p.x; a0.y += p.y; a0.z += q.x; a0.w += q.y;
        p = __half22float2(*reinterpret_cast<__half2*>(&u1.x));
        q = __half22float2(*reinterpret_cast<__half2*>(&u1.y));
        a1.x += p.x; a1.y += p.y; a1.z += q.x; a1.w += q.y;
        p = __half22float2(*reinterpret_cast<__half2*>(&u2.x));
        q = __half22float2(*reinterpret_cast<__half2*>(&u2.y));
        a2.x += p.x; a2.y += p.y; a2.z += q.x; a2.w += q.y;
        p = __half22float2(*reinterpret_cast<__half2*>(&u3.x));
        q = __half22float2(*reinterpret_cast<__half2*>(&u3.y));
        a3.x += p.x; a3.y += p.y; a3.z += q.x; a3.w += q.y;
    }
    for (; e < s1; e++) {
        int i0 = __ldg(&adj[e]);
        uint2 u0 = *(const uint2*)(xs + (size_t)i0 * DIMN + lane * 4);
        float2 p = __half22float2(*reinterpret_cast<__half2*>(&u0.x));
        float2 q = __half22float2(*reinterpret_cast<__half2*>(&u0.y));
        a0.x += p.x; a0.y += p.y; a0.z += q.x; a0.w += q.y;
    }
    a0.x += a1.x + a2.x + a3.x;
    a0.y += a1.y + a2.y + a3.y;
    a0.z += a1.z + a2.z + a3.z;
    a0.w += a1.w + a2.w + a3.w;
    int deg = s1 - s0;
    float inv = 1.0f / (float)(deg > 0 ? deg : 1);
    __half2 h0 = __floats2half2_rn(a0.x * inv, a0.y * inv);
    __half2 h1 = __floats2half2_rn(a0.z * inv, a0.w * inv);
    uint2 u;
    u.x = *reinterpret_cast<uint32_t*>(&h0);
    u.y = *reinterpret_cast<uint32_t*>(&h1);
    *(uint2*)(mean + (size_t)node * DIMN + lane * 4) = u;
}

// ---------------- mma.sync helpers ----------------
__device__ __forceinline__ uint32_t smem_u32(const void* p) {
    uint32_t a;
    asm("{ .reg .u64 t; cvta.to.shared.u64 t, %1; cvt.u32.u64 %0, t; }"
        : "=r"(a) : "l"(p));
    return a;
}
__device__ __forceinline__ void ldsm4(uint32_t* r, uint32_t addr) {
    asm volatile("ldmatrix.sync.aligned.m8n8.x4.shared.b16 {%0,%1,%2,%3}, [%4];"
                 : "=r"(r[0]), "=r"(r[1]), "=r"(r[2]), "=r"(r[3]) : "r"(addr));
}
__device__ __forceinline__ void mma16816(float* d, const uint32_t* a,
                                         uint32_t b0, uint32_t b1) {
    asm volatile(
        "mma.sync.aligned.m16n8k16.row.col.f32.bf16.bf16.f32 "
        "{%0,%1,%2,%3}, {%4,%5,%6,%7}, {%8,%9}, {%0,%1,%2,%3};"
        : "+f"(d[0]), "+f"(d[1]), "+f"(d[2]), "+f"(d[3])
        : "r"(a[0]), "r"(a[1]), "r"(a[2]), "r"(a[3]), "r"(b0), "r"(b1));
}
__device__ __forceinline__ void cpa16(uint32_t dst, const void* src) {
    asm volatile("cp.async.ca.shared.global [%0], [%1], 16;"
                 :: "r"(dst), "l"(src) : "memory");
}
#define CPA_COMMIT() asm volatile("cp.async.commit_group;" ::: "memory")
#define CPA_WAIT0()  asm volatile("cp.async.wait_group 0;" ::: "memory")

// ---------------- tensor-core GEMM core: fp16 A panels ----------------
#define TSTRIDE 72   // elements; 144 bytes

template <int NP>
__device__ __forceinline__ void gemm_core(const __half* const* Ap, const int* wp,
                                          float* __restrict__ Cout,
                                          const float* __restrict__ bias,
                                          int M, int m0)
{
    extern __shared__ __nv_bfloat16 smem[];
    __nv_bfloat16* Ah = smem;
    __nv_bfloat16* Al = Ah + 128 * TSTRIDE;
    __nv_bfloat16* Wh = Al + 128 * TSTRIDE;
    __nv_bfloat16* Wl = Wh + 128 * TSTRIDE;
    const uint32_t sAh = smem_u32(Ah);
    const uint32_t sAl = smem_u32(Al);
    const uint32_t sWh = smem_u32(Wh);
    const uint32_t sWl = smem_u32(Wl);

    int tid = threadIdx.x, w = tid >> 5, lane = tid & 31;
    int wm = w & 3;          // m-strip: rows [wm*32, wm*32+32)
    int wn = w >> 2;         // n-half:  cols [wn*64, wn*64+64)

    float acc[2][8][4];
    #pragma unroll
    for (int s = 0; s < 2; s++)
        #pragma unroll
        for (int i = 0; i < 8; i++)
            #pragma unroll
            for (int j = 0; j < 4; j++) acc[s][i][j] = 0.f;

    int a_row = lane & 15;
    int a_kh  = (lane >> 4) << 3;
    int b_n   = (lane & 7) + ((lane >> 4) << 3);
    int b_kh  = ((lane >> 3) & 1) << 3;

    #pragma unroll
    for (int p = 0; p < NP; p++) {
        const __half* A = Ap[p];
        const __nv_bfloat16* WHsrc = g_Wsp[wp[p]][0];
        const __nv_bfloat16* WLsrc = g_Wsp[wp[p]][1];
        for (int c = 0; c < 2; c++) {
            __syncthreads();   // protect previous iteration's smem reads
            // ---- W chunk via cp.async (overlaps with A convert below)
            #pragma unroll
            for (int it = 0; it < 4; it++) {
                int q = tid + it * 256;
                int n = q >> 3;
                int j = q & 7;
                cpa16(sWh + (n * TSTRIDE + j * 8) * 2, WHsrc + n * 128 + c * 64 + j * 8);
                cpa16(sWl + (n * TSTRIDE + j * 8) * 2, WLsrc + n * 128 + c * 64 + j * 8);
            }
            CPA_COMMIT();
            // ---- load fp16 & split A chunk [128 m x 64 k]
            #pragma unroll
            for (int it = 0; it < 8; it++) {
                int q = tid + it * 256;
                int row = q >> 4;
                int k4  = (q & 15) << 2;
                int grow = m0 + row;
                float4 v = make_float4(0.f, 0.f, 0.f, 0.f);
                if (grow < M) {
                    uint2 u = *(const uint2*)(A + (size_t)grow * DIMN + c * 64 + k4);
                    float2 p2 = __half22float2(*reinterpret_cast<__half2*>(&u.x));
                    float2 q2 = __half22float2(*reinterpret_cast<__half2*>(&u.y));
                    v = make_float4(p2.x, p2.y, q2.x, q2.y);
                }
                __nv_bfloat16 h0 = __float2bfloat16_rn(v.x);
                __nv_bfloat16 h1 = __float2bfloat16_rn(v.y);
                __nv_bfloat16 h2 = __float2bfloat16_rn(v.z);
                __nv_bfloat16 h3 = __float2bfloat16_rn(v.w);
                ushort4 uh = make_ushort4(__bfloat16_as_ushort(h0), __bfloat16_as_ushort(h1),
                                          __bfloat16_as_ushort(h2), __bfloat16_as_ushort(h3));
                __nv_bfloat16 l0 = __float2bfloat16_rn(v.x - __bfloat162float(h0));
                __nv_bfloat16 l1 = __float2bfloat16_rn(v.y - __bfloat162float(h1));
                __nv_bfloat16 l2 = __float2bfloat16_rn(v.z - __bfloat162float(h2));
                __nv_bfloat16 l3 = __float2bfloat16_rn(v.w - __bfloat162float(h3));
                ushort4 ul = make_ushort4(__bfloat16_as_ushort(l0), __bfloat16_as_ushort(l1),
                                          __bfloat16_as_ushort(l2), __bfloat16_as_ushort(l3));
                *(ushort4*)(Ah + row * TSTRIDE + k4) = uh;
                *(ushort4*)(Al + row * TSTRIDE + k4) = ul;
            }
            CPA_WAIT0();
            __syncthreads();
            // ---- compute: warp (wm, wn) owns m32 x n64
            #pragma unroll
            for (int ks = 0; ks < 4; ks++) {
                uint32_t aH[2][4], aL[2][4];
                #pragma unroll
                for (int s = 0; s < 2; s++) {
                    uint32_t aoff = (uint32_t)((wm * 32 + s * 16 + a_row) * TSTRIDE
                                               + ks * 16 + a_kh) * 2;
                    ldsm4(aH[s], sAh + aoff);
                    ldsm4(aL[s], sAl + aoff);
                }
                #pragma unroll
                for (int nt = 0; nt < 4; nt++) {
                    uint32_t bH[4], bL[4];
                    uint32_t boff = (uint32_t)((wn * 64 + nt * 16 + b_n) * TSTRIDE
                                               + ks * 16 + b_kh) * 2;
                    ldsm4(bH, sWh + boff);
                    ldsm4(bL, sWl + boff);
                    #pragma unroll
                    for (int s = 0; s < 2; s++) {
                        mma16816(acc[s][nt * 2],     aH[s], bH[0], bH[1]);
                        mma16816(acc[s][nt * 2 + 1], aH[s], bH[2], bH[3]);
                        mma16816(acc[s][nt * 2],     aH[s], bL[0], bL[1]);
                        mma16816(acc[s][nt * 2 + 1], aH[s], bL[2], bL[3]);
                        mma16816(acc[s][nt * 2],     aL[s], bH[0], bH[1]);
                        mma16816(acc[s][nt * 2 + 1], aL[s], bH[2], bH[3]);
                    }
                }
            }
        }
    }

    // ---- epilogue
    int ncol = (lane & 3) * 2;
    #pragma unroll
    for (int s = 0; s < 2; s++) {
        int row0 = m0 + wm * 32 + s * 16 + (lane >> 2);
        int row1 = row0 + 8;
        #pragma unroll
        for (int t8 = 0; t8 < 8; t8++) {
            int n = wn * 64 + t8 * 8 + ncol;
            float2 bv = *(const float2*)(bias + n);
            if (row0 < M) {
                float2 o = make_float2(acc[s][t8][0] + bv.x, acc[s][t8][1] + bv.y);
                *(float2*)(Cout + (size_t)row0 * DIMN + n) = o;
            }
            if (row1 < M) {
                float2 o = make_float2(acc[s][t8][2] + bv.x, acc[s][t8][3] + bv.y);
                *(float2*)(Cout + (size_t)row1 * DIMN + n) = o;
            }
        }
    }
}

__global__ void __launch_bounds__(256, 2)
k_gemm_user(float* __restrict__ out, int NU) {
    const __half* Ap[2] = {g_meanRh, g_xuh};
    const int wp[2] = {0, 1};
    gemm_core<2>(Ap, wp, out, g_biasU, NU, blockIdx.x * 128);
}

__global__ void __launch_bounds__(256, 2)
k_gemm_item(float* __restrict__ out, int NI) {
    const __half* Ap[3] = {g_meanBh, g_meanTh, g_xih};
    const int wp[3] = {2, 3, 4};
    gemm_core<3>(Ap, wp, out, g_biasI, NI, blockIdx.x * 128);
}

// ---------------- launch: two-stream pipelined graph ----------------
extern "C" void kernel_launch(void* const* d_in, const int* in_sizes, int n_in,
                              void* d_out, int out_size) {
    const float* xu  = (const float*)d_in[0];
    const float* xi  = (const float*)d_in[1];
    const float* xt  = (const float*)d_in[2];
    const int*   eb  = (const int*)d_in[3];
    const int*   er  = (const int*)d_in[4];
    const int*   et  = (const int*)d_in[5];
    const float* WlB = (const float*)d_in[6];
    const float* WrB = (const float*)d_in[7];
    const float* bB  = (const float*)d_in[8];
    const float* WlR = (const float*)d_in[9];
    const float* WrR = (const float*)d_in[10];
    const float* bR  = (const float*)d_in[11];
    const float* WlT = (const float*)d_in[12];
    const float* WrT = (const float*)d_in[13];
    const float* bT  = (const float*)d_in[14];

    int NU = in_sizes[0] / DIMN;
    int NI = in_sizes[1] / DIMN;
    int NT = in_sizes[2] / DIMN;
    int EB = in_sizes[3] / 2;
    int ER = in_sizes[4] / 2;
    int ET = in_sizes[5] / 2;

    float* out_user = (float*)d_out;
    float* out_item = (float*)d_out + (size_t)NU * DIMN;

    __half* dmB; cudaGetSymbolAddress((void**)&dmB, g_meanBh);
    __half* dmR; cudaGetSymbolAddress((void**)&dmR, g_meanRh);
    __half* dmT; cudaGetSymbolAddress((void**)&dmT, g_meanTh);
    __half* xuh; cudaGetSymbolAddress((void**)&xuh, g_xuh);
    __half* xih; cudaGetSymbolAddress((void**)&xih, g_xih);
    __half* xth; cudaGetSymbolAddress((void**)&xth, g_xth);

    const int SMEM_BYTES = 4 * 128 * TSTRIDE * 2;   // 73728
    cudaFuncSetAttribute(k_gemm_user, cudaFuncAttributeMaxDynamicSharedMemorySize, SMEM_BYTES);
    cudaFuncSetAttribute(k_gemm_item, cudaFuncAttributeMaxDynamicSharedMemorySize, SMEM_BYTES);

    int nblkU = (NU + 1023) / 1024;
    int nblkI = (NI + 1023) / 1024;

    cudaStream_t s0 = 0;  // capture-origin (legacy) stream

    // init: zero counters + weight prep, then fork
    k_init<<<(3 * (NU_MAX + 1) + 255) / 256, 256, 0, s0>>>(WlR, WrR, WlB, WlT,
                                                           WrB, WrT, bR, bB, bT);
    cudaEventRecord(g_sk.ev0, s0);
    cudaStreamWaitEvent(g_sk.sA, g_sk.ev0, 0);
    cudaStreamWaitEvent(g_sk.sB, g_sk.ev0, 0);

    // ---- conversions first on both streams; record BOTH events before any wait
    {
        int n = NI * DIMN;
        k_tohalf<<<(n / 4 + 255) / 256, 256, 0, g_sk.sA>>>(xi, xih, n);
    }
    cudaEventRecord(g_sk.evCA, g_sk.sA);   // xih ready
    {
        int n = NU * DIMN;
        k_tohalf<<<(n / 4 + 255) / 256, 256, 0, g_sk.sB>>>(xu, xuh, n);
        int m = NT * DIMN;
        k_tohalf<<<(m / 4 + 255) / 256, 256, 0, g_sk.sB>>>(xt, xth, m);
    }
    cudaEventRecord(g_sk.evCB, g_sk.sB);   // xuh, xth ready

    // ---- stream A: rel 1 (rev) -> out_user
    k_hist1<<<(ER / 2 + 255) / 256, 256, 0, g_sk.sA>>>(er + ER, ER, 1);
    k_scan1<<<nblkU, 1024, 0, g_sk.sA>>>(1, NU);
    k_scan2<<<1, 1024, 0, g_sk.sA>>>(1, nblkU, NU, 1, nblkU, NU);
    k_scan3<<<(NU + 255) / 256, 256, 0, g_sk.sA>>>(1, NU);
    k_fill1<<<(ER / 2 + 255) / 256, 256, 0, g_sk.sA>>>(er, ER, 1);
    k_agg1<<<(NU * 32 + 255) / 256, 256, 0, g_sk.sA>>>(xih, dmR, 1, NU);
    cudaStreamWaitEvent(g_sk.sA, g_sk.evCB, 0);   // need xuh for root panel
    k_gemm_user<<<(NU + 127) / 128, 256, SMEM_BYTES, g_sk.sA>>>(out_user, NU);
    cudaEventRecord(g_sk.evA, g_sk.sA);

    // ---- stream B: rels 0 (buys), 2 (tags) -> out_item
    k_hist1<<<(EB / 2 + 255) / 256, 256, 0, g_sk.sB>>>(eb + EB, EB, 0);
    k_hist1<<<(ET / 2 + 255) / 256, 256, 0, g_sk.sB>>>(et + ET, ET, 2);
    k_scan1<<<nblkI, 1024, 0, g_sk.sB>>>(0, NI);
    k_scan1<<<nblkI, 1024, 0, g_sk.sB>>>(2, NI);
    k_scan2<<<2, 1024, 0, g_sk.sB>>>(0, nblkI, NI, 2, nblkI, NI);
    k_scan3<<<(NI + 255) / 256, 256, 0, g_sk.sB>>>(0, NI);
    k_scan3<<<(NI + 255) / 256, 256, 0, g_sk.sB>>>(2, NI);
    k_fill1<<<(EB / 2 + 255) / 256, 256, 0, g_sk.sB>>>(eb, EB, 0);
    k_fill1<<<(ET / 2 + 255) / 256, 256, 0, g_sk.sB>>>(et, ET, 2);
    k_agg1<<<(NI * 32 + 255) / 256, 256, 0, g_sk.sB>>>(xuh, dmB, 0, NI);
    k_agg1<<<(NI * 32 + 255) / 256, 256, 0, g_sk.sB>>>(xth, dmT, 2, NI);
    cudaStreamWaitEvent(g_sk.sB, g_sk.evCA, 0);   // need xih for root panel
    k_gemm_item<<<(NI + 127) / 128, 256, SMEM_BYTES, g_sk.sB>>>(out_item, NI);
    cudaEventRecord(g_sk.evB, g_sk.sB);

    // ---- join back to origin stream
    cudaStreamWaitEvent(s0, g_sk.evA, 0);
    cudaStreamWaitEvent(s0, g_sk.evB, 0);
}

// round 17
// speedup vs baseline: 1.3761x; 1.0684x over previous
#include <cuda_runtime.h>
#include <cuda_bf16.h>
#include <cuda_fp16.h>
#include <cstddef>
#include <cstdint>

#define NU_MAX 100000
#define NI_MAX 100000
#define E_MAX  1000000
#define DIMN   128

// ---------------- scratch (static __device__, no allocation) ----------------
__device__ int   g_cnt[3][NU_MAX + 1];
__device__ int   g_off[3][NU_MAX + 1];
__device__ int   g_cur[3][NU_MAX];
__device__ int   g_adj[3][E_MAX];
__device__ int   g_bsum[3][1024];

// fp16 means (fp32-accumulated, rounded once)
__device__ __align__(16) __half g_meanBh[(size_t)NI_MAX * DIMN];
__device__ __align__(16) __half g_meanRh[(size_t)NU_MAX * DIMN];
__device__ __align__(16) __half g_meanTh[(size_t)NI_MAX * DIMN];

// fp16 copies of node features
__device__ __align__(16) __half g_xuh[(size_t)NU_MAX * DIMN];
__device__ __align__(16) __half g_xih[(size_t)NI_MAX * DIMN];
__device__ __align__(16) __half g_xth[(size_t)NU_MAX * DIMN];  // sized safe

// split + transposed weights: [panel][half hi/lo][n*128+k] bf16
__device__ __align__(16) __nv_bfloat16 g_Wsp[5][2][DIMN * DIMN];
__device__ __align__(16) float g_biasU[DIMN];
__device__ __align__(16) float g_biasI[DIMN];

// ---------------- host-side streams/events (created once, before capture) ----
namespace {
struct StreamKit {
    cudaStream_t sA, sB;
    cudaEvent_t ev0, evA, evB, evCA, evCB;
    StreamKit() {
        cudaStreamCreateWithFlags(&sA, cudaStreamNonBlocking);
        cudaStreamCreateWithFlags(&sB, cudaStreamNonBlocking);
        cudaEventCreateWithFlags(&ev0, cudaEventDisableTiming);
        cudaEventCreateWithFlags(&evA, cudaEventDisableTiming);
        cudaEventCreateWithFlags(&evB, cudaEventDisableTiming);
        cudaEventCreateWithFlags(&evCA, cudaEventDisableTiming);
        cudaEventCreateWithFlags(&evCB, cudaEventDisableTiming);
    }
};
StreamKit g_sk;
}

// ---------------- init: zero counters + weight prep (merged) ----------------
__global__ void k_init(const float* __restrict__ WlR, const float* __restrict__ WrR,
                       const float* __restrict__ WlB, const float* __restrict__ WlT,
                       const float* __restrict__ WrB, const float* __restrict__ WrT,
                       const float* __restrict__ bR, const float* __restrict__ bB,
                       const float* __restrict__ bT) {
    int i = blockIdx.x * blockDim.x + threadIdx.x;
    const int total = 3 * (NU_MAX + 1);
    if (i < total) ((int*)g_cnt)[i] = 0;
    if (i < 5 * 16384) {
        int panel = i >> 14;
        int e = i & 16383;
        int k = e >> 7;
        int n = e & 127;
        float v;
        switch (panel) {
            case 0:  v = WlR[k * 128 + n]; break;
            case 1:  v = WrR[k * 128 + n]; break;
            case 2:  v = 0.5f * WlB[k * 128 + n]; break;
            case 3:  v = 0.5f * WlT[k * 128 + n]; break;
            default: v = 0.5f * (WrB[k * 128 + n] + WrT[k * 128 + n]);
        }
        __nv_bfloat16 h = __float2bfloat16_rn(v);
        __nv_bfloat16 l = __float2bfloat16_rn(v - __bfloat162float(h));
        g_Wsp[panel][0][n * 128 + k] = h;
        g_Wsp[panel][1][n * 128 + k] = l;
    }
    if (i < DIMN) {
        g_biasU[i] = bR[i];
        g_biasI[i] = 0.5f * (bB[i] + bT[i]);
    }
}

// ---------------- fp32 -> fp16 feature conversion ----------------
__global__ void k_tohalf(const float* __restrict__ x, __half* __restrict__ xh, int n) {
    int i = (blockIdx.x * blockDim.x + threadIdx.x) * 4;
    if (i < n) {
        float4 v = *(const float4*)(x + i);
        __half2 a = __floats2half2_rn(v.x, v.y);
        __half2 b = __floats2half2_rn(v.z, v.w);
        uint2 u;
        u.x = *reinterpret_cast<uint32_t*>(&a);
        u.y = *reinterpret_cast<uint32_t*>(&b);
        *(uint2*)(xh + i) = u;
    }
}

// merged: two tensors in one launch
__global__ void k_tohalf2(const float* __restrict__ x0, __half* __restrict__ h0, int n0,
                          const float* __restrict__ x1, __half* __restrict__ h1, int n1) {
    int i = (blockIdx.x * blockDim.x + threadIdx.x) * 4;
    const float* x;
    __half* h;
    if (i < n0) { x = x0 + i; h = h0 + i; }
    else if (i < n0 + n1) { x = x1 + (i - n0); h = h1 + (i - n0); }
    else return;
    float4 v = *(const float4*)x;
    __half2 a = __floats2half2_rn(v.x, v.y);
    __half2 b = __floats2half2_rn(v.z, v.w);
    uint2 u;
    u.x = *reinterpret_cast<uint32_t*>(&a);
    u.y = *reinterpret_cast<uint32_t*>(&b);
    *(uint2*)h = u;
}

// ---------------- CSR build ----------
__global__ void k_hist1(const int* __restrict__ dst, int E, int rel) {
    int t = blockIdx.x * blockDim.x + threadIdx.x;
    #pragma unroll
    for (int j = 0; j < 2; j++) {
        int e = t * 2 + j;
        if (e < E) atomicAdd(&g_cnt[rel][dst[e]], 1);
    }
}

// merged: rels 0 and 2 in one launch
__global__ void k_hist2rel(const int* __restrict__ d0, const int* __restrict__ d2,
                           int E0, int E2) {
    int t = blockIdx.x * blockDim.x + threadIdx.x;
    #pragma unroll
    for (int j = 0; j < 2; j++) {
        int e = t * 2 + j;
        if (e < E0) atomicAdd(&g_cnt[0][d0[e]], 1);
        else if (e < E0 + E2) atomicAdd(&g_cnt[2][d2[e - E0]], 1);
    }
}

// ---------------- parallel 3-pass exclusive scan (grid.y selects relation) --
__global__ void k_scan1p(int r0, int r1, int n) {
    int rel = (blockIdx.y == 0) ? r0 : r1;
    int tid = threadIdx.x;
    int i = blockIdx.x * 1024 + tid;
    int lane = tid & 31, wid = tid >> 5;
    __shared__ int wsum[32];
    int v = (i < n) ? g_cnt[rel][i] : 0;
    int s = v;
    #pragma unroll
    for (int d = 1; d < 32; d <<= 1) {
        int t = __shfl_up_sync(0xFFFFFFFFu, s, d);
        if (lane >= d) s += t;
    }
    if (lane == 31) wsum[wid] = s;
    __syncthreads();
    if (wid == 0) {
        int w = wsum[lane];
        #pragma unroll
        for (int d = 1; d < 32; d <<= 1) {
            int t = __shfl_up_sync(0xFFFFFFFFu, w, d);
            if (lane >= d) w += t;
        }
        wsum[lane] = w;
    }
    __syncthreads();
    int woff = (wid > 0) ? wsum[wid - 1] : 0;
    if (i < n) g_off[rel][i] = woff + s - v;
    if (tid == 1023) g_bsum[rel][blockIdx.x] = woff + s;
}

__global__ void k_scan2(int r0, int nblk0, int n0, int r1, int nblk1, int n1) {
    int rel  = (blockIdx.x == 0) ? r0 : r1;
    int nblk = (blockIdx.x == 0) ? nblk0 : nblk1;
    int n    = (blockIdx.x == 0) ? n0 : n1;
    int tid = threadIdx.x;
    int lane = tid & 31, wid = tid >> 5;
    __shared__ int wsum[32];
    int v = (tid < nblk) ? g_bsum[rel][tid] : 0;
    int s = v;
    #pragma unroll
    for (int d = 1; d < 32; d <<= 1) {
        int t = __shfl_up_sync(0xFFFFFFFFu, s, d);
        if (lane >= d) s += t;
    }
    if (lane == 31) wsum[wid] = s;
    __syncthreads();
    if (wid == 0) {
        int w = wsum[lane];
        #pragma unroll
        for (int d = 1; d < 32; d <<= 1) {
            int t = __shfl_up_sync(0xFFFFFFFFu, w, d);
            if (lane >= d) w += t;
        }
        wsum[lane] = w;
    }
    __syncthreads();
    int woff = (wid > 0) ? wsum[wid - 1] : 0;
    if (tid < nblk) g_bsum[rel][tid] = woff + s - v;
    if (tid == 1023) g_off[rel][n] = woff + s;
}

__global__ void k_scan3p(int r0, int r1, int n) {
    int rel = (blockIdx.y == 0) ? r0 : r1;
    int i = blockIdx.x * 256 + threadIdx.x;
    if (i < n) {
        int off = g_off[rel][i] + g_bsum[rel][i >> 10];
        g_off[rel][i] = off;
        g_cur[rel][i] = off;
    }
}

__global__ void k_fill1(const int* __restrict__ ei, int E, int rel) {
    int t = blockIdx.x * blockDim.x + threadIdx.x;
    #pragma unroll
    for (int j = 0; j < 2; j++) {
        int e = t * 2 + j;
        if (e < E) {
            int d = ei[E + e];
            int s = ei[e];
            int p = atomicAdd(&g_cur[rel][d], 1);
            g_adj[rel][p] = s;
        }
    }
}

// merged: rels 0 and 2 in one launch
__global__ void k_fill2rel(const int* __restrict__ e0, const int* __restrict__ e2,
                           int E0, int E2) {
    int t = blockIdx.x * blockDim.x + threadIdx.x;
    #pragma unroll
    for (int j = 0; j < 2; j++) {
        int e = t * 2 + j;
        int rel, idx, E;
        const int* ei;
        if (e < E0) { rel = 0; idx = e; ei = e0; E = E0; }
        else if (e < E0 + E2) { rel = 2; idx = e - E0; ei = e2; E = E2; }
        else continue;
        int d = ei[E + idx];
        int s = ei[idx];
        int p = atomicAdd(&g_cur[rel][d], 1);
        g_adj[rel][p] = s;
    }
}

// ---------------- mean aggregation: fp16 gather, fp32 accumulate, fp16 store
__device__ __forceinline__ void agg_body(const __half* __restrict__ xs,
                                         __half* __restrict__ mean,
                                         int rel, int node, int lane) {
    const int* __restrict__ adj = g_adj[rel];
    int s0 = g_off[rel][node], s1 = g_off[rel][node + 1];
    float4 a0 = make_float4(0.f, 0.f, 0.f, 0.f);
    float4 a1 = make_float4(0.f, 0.f, 0.f, 0.f);
    float4 a2 = make_float4(0.f, 0.f, 0.f, 0.f);
    float4 a3 = make_float4(0.f, 0.f, 0.f, 0.f);
    int e = s0;
    for (; e + 3 < s1; e += 4) {
        int i0 = __ldg(&adj[e]);
        int i1 = __ldg(&adj[e + 1]);
        int i2 = __ldg(&adj[e + 2]);
        int i3 = __ldg(&adj[e + 3]);
        uint2 u0 = *(const uint2*)(xs + (size_t)i0 * DIMN + lane * 4);
        uint2 u1 = *(const uint2*)(xs + (size_t)i1 * DIMN + lane * 4);
        uint2 u2 = *(const uint2*)(xs + (size_t)i2 * DIMN + lane * 4);
        uint2 u3 = *(const uint2*)(xs + (size_t)i3 * DIMN + lane * 4);
        float2 p, q;
        p = __half22float2(*reinterpret_cast<__half2*>(&u0.x));
        q = __half22float2(*reinterpret_cast<__half2*>(&u0.y));
        a0.x += p.x; a0.y += p.y; a0.z += q.x; a0.w += q.y;
        p = __half22float2(*reinterpret_cast<__half2*>(&u1.x));
        q = __half22float2(*reinterpret_cast<__half2*>(&u1.y));
        a1.x += p.x; a1.y += p.y; a1.z += q.x; a1.w += q.y;
        p = __half22float2(*reinterpret_cast<__half2*>(&u2.x));
        q = __half22float2(*reinterpret_cast<__half2*>(&u2.y));
        a2.x += p.x; a2.y += p.y; a2.z += q.x; a2.w += q.y;
        p = __half22float2(*reinterpret_cast<__half2*>(&u3.x));
        q = __half22float2(*reinterpret_cast<__half2*>(&u3.y));
        a3.x += p.x; a3.y += p.y; a3.z += q.x; a3.w += q.y;
    }
    for (; e < s1; e++) {
        int i0 = __ldg(&adj[e]);
        uint2 u0 = *(const uint2*)(xs + (size_t)i0 * DIMN + lane * 4);
        float2 p = __half22float2(*reinterpret_cast<__half2*>(&u0.x));
        float2 q = __half22float2(*reinterpret_cast<__half2*>(&u0.y));
        a0.x += p.x; a0.y += p.y; a0.z += q.x; a0.w += q.y;
    }
    a0.x += a1.x + a2.x + a3.x;
    a0.y += a1.y + a2.y + a3.y;
    a0.z += a1.z + a2.z + a3.z;
    a0.w += a1.w + a2.w + a3.w;
    int deg = s1 - s0;
    float inv = 1.0f / (float)(deg > 0 ? deg : 1);
    __half2 h0 = __floats2half2_rn(a0.x * inv, a0.y * inv);
    __half2 h1 = __floats2half2_rn(a0.z * inv, a0.w * inv);
    uint2 u;
    u.x = *reinterpret_cast<uint32_t*>(&h0);
    u.y = *reinterpret_cast<uint32_t*>(&h1);
    *(uint2*)(mean + (size_t)node * DIMN + lane * 4) = u;
}

__global__ void k_agg1(const __half* __restrict__ xs, __half* __restrict__ mean,
                       int rel, int n_dst) {
    int node = (blockIdx.x * blockDim.x + threadIdx.x) >> 5;
    int lane = threadIdx.x & 31;
    if (node >= n_dst) return;
    agg_body(xs, mean, rel, node, lane);
}

// merged: rels 0 and 2 in one launch
__global__ void k_agg2rel(const __half* __restrict__ xs0, __half* __restrict__ m0,
                          const __half* __restrict__ xs2, __half* __restrict__ m2,
                          int NI) {
    int w = (blockIdx.x * blockDim.x + threadIdx.x) >> 5;
    int lane = threadIdx.x & 31;
    if (w < NI) agg_body(xs0, m0, 0, w, lane);
    else if (w < 2 * NI) agg_body(xs2, m2, 2, w - NI, lane);
}

// ---------------- mma.sync helpers ----------------
__device__ __forceinline__ uint32_t smem_u32(const void* p) {
    uint32_t a;
    asm("{ .reg .u64 t; cvta.to.shared.u64 t, %1; cvt.u32.u64 %0, t; }"
        : "=r"(a) : "l"(p));
    return a;
}
__device__ __forceinline__ void ldsm4(uint32_t* r, uint32_t addr) {
    asm volatile("ldmatrix.sync.aligned.m8n8.x4.shared.b16 {%0,%1,%2,%3}, [%4];"
                 : "=r"(r[0]), "=r"(r[1]), "=r"(r[2]), "=r"(r[3]) : "r"(addr));
}
__device__ __forceinline__ void mma16816(float* d, const uint32_t* a,
                                         uint32_t b0, uint32_t b1) {
    asm volatile(
        "mma.sync.aligned.m16n8k16.row.col.f32.bf16.bf16.f32 "
        "{%0,%1,%2,%3}, {%4,%5,%6,%7}, {%8,%9}, {%0,%1,%2,%3};"
        : "+f"(d[0]), "+f"(d[1]), "+f"(d[2]), "+f"(d[3])
        : "r"(a[0]), "r"(a[1]), "r"(a[2]), "r"(a[3]), "r"(b0), "r"(b1));
}
__device__ __forceinline__ void cpa16(uint32_t dst, const void* src) {
    asm volatile("cp.async.ca.shared.global [%0], [%1], 16;"
                 :: "r"(dst), "l"(src) : "memory");
}
#define CPA_COMMIT() asm volatile("cp.async.commit_group;" ::: "memory")
#define CPA_WAIT0()  asm volatile("cp.async.wait_group 0;" ::: "memory")

// ---------------- tensor-core GEMM core: fp16 A panels ----------------
#define TSTRIDE 72   // elements; 144 bytes

template <int NP>
__device__ __forceinline__ void gemm_core(const __half* const* Ap, const int* wp,
                                          float* __restrict__ Cout,
                                          const float* __restrict__ bias,
                                          int M, int m0)
{
    extern __shared__ __nv_bfloat16 smem[];
    __nv_bfloat16* Ah = smem;
    __nv_bfloat16* Al = Ah + 128 * TSTRIDE;
    __nv_bfloat16* Wh = Al + 128 * TSTRIDE;
    __nv_bfloat16* Wl = Wh + 128 * TSTRIDE;
    const uint32_t sAh = smem_u32(Ah);
    const uint32_t sAl = smem_u32(Al);
    const uint32_t sWh = smem_u32(Wh);
    const uint32_t sWl = smem_u32(Wl);

    int tid = threadIdx.x, w = tid >> 5, lane = tid & 31;
    int wm = w & 3;          // m-strip: rows [wm*32, wm*32+32)
    int wn = w >> 2;         // n-half:  cols [wn*64, wn*64+64)

    float acc[2][8][4];
    #pragma unroll
    for (int s = 0; s < 2; s++)
        #pragma unroll
        for (int i = 0; i < 8; i++)
            #pragma unroll
            for (int j = 0; j < 4; j++) acc[s][i][j] = 0.f;

    int a_row = lane & 15;
    int a_kh  = (lane >> 4) << 3;
    int b_n   = (lane & 7) + ((lane >> 4) << 3);
    int b_kh  = ((lane >> 3) & 1) << 3;

    #pragma unroll
    for (int p = 0; p < NP; p++) {
        const __half* A = Ap[p];
        const __nv_bfloat16* WHsrc = g_Wsp[wp[p]][0];
        const __nv_bfloat16* WLsrc = g_Wsp[wp[p]][1];
        for (int c = 0; c < 2; c++) {
            __syncthreads();   // protect previous iteration's smem reads
            // ---- W chunk via cp.async (overlaps with A convert below)
            #pragma unroll
            for (int it = 0; it < 4; it++) {
                int q = tid + it * 256;
                int n = q >> 3;
                int j = q & 7;
                cpa16(sWh + (n * TSTRIDE + j * 8) * 2, WHsrc + n * 128 + c * 64 + j * 8);
                cpa16(sWl + (n * TSTRIDE + j * 8) * 2, WLsrc + n * 128 + c * 64 + j * 8);
            }
            CPA_COMMIT();
            // ---- load fp16 & split A chunk [128 m x 64 k]
            #pragma unroll
            for (int it = 0; it < 8; it++) {
                int q = tid + it * 256;
                int row = q >> 4;
                int k4  = (q & 15) << 2;
                int grow = m0 + row;
                float4 v = make_float4(0.f, 0.f, 0.f, 0.f);
                if (grow < M) {
                    uint2 u = *(const uint2*)(A + (size_t)grow * DIMN + c * 64 + k4);
                    float2 p2 = __half22float2(*reinterpret_cast<__half2*>(&u.x));
                    float2 q2 = __half22float2(*reinterpret_cast<__half2*>(&u.y));
                    v = make_float4(p2.x, p2.y, q2.x, q2.y);
                }
                __nv_bfloat16 h0 = __float2bfloat16_rn(v.x);
                __nv_bfloat16 h1 = __float2bfloat16_rn(v.y);
                __nv_bfloat16 h2 = __float2bfloat16_rn(v.z);
                __nv_bfloat16 h3 = __float2bfloat16_rn(v.w);
                ushort4 uh = make_ushort4(__bfloat16_as_ushort(h0), __bfloat16_as_ushort(h1),
                                          __bfloat16_as_ushort(h2), __bfloat16_as_ushort(h3));
                __nv_bfloat16 l0 = __float2bfloat16_rn(v.x - __bfloat162float(h0));
                __nv_bfloat16 l1 = __float2bfloat16_rn(v.y - __bfloat162float(h1));
                __nv_bfloat16 l2 = __float2bfloat16_rn(v.z - __bfloat162float(h2));
                __nv_bfloat16 l3 = __float2bfloat16_rn(v.w - __bfloat162float(h3));
                ushort4 ul = make_ushort4(__bfloat16_as_ushort(l0), __bfloat16_as_ushort(l1),
                                          __bfloat16_as_ushort(l2), __bfloat16_as_ushort(l3));
                *(ushort4*)(Ah + row * TSTRIDE + k4) = uh;
                *(ushort4*)(Al + row * TSTRIDE + k4) = ul;
            }
            CPA_WAIT0();
            __syncthreads();
            // ---- compute: warp (wm, wn) owns m32 x n64
            #pragma unroll
            for (int ks = 0; ks < 4; ks++) {
                uint32_t aH[2][4], aL[2][4];
                #pragma unroll
                for (int s = 0; s < 2; s++) {
                    uint32_t aoff = (uint32_t)((wm * 32 + s * 16 + a_row) * TSTRIDE
                                               + ks * 16 + a_kh) * 2;
                    ldsm4(aH[s], sAh + aoff);
                    ldsm4(aL[s], sAl + aoff);
                }
                #pragma unroll
                for (int nt = 0; nt < 4; nt++) {
                    uint32_t bH[4], bL[4];
                    uint32_t boff = (uint32_t)((wn * 64 + nt * 16 + b_n) * TSTRIDE
                                               + ks * 16 + b_kh) * 2;
                    ldsm4(bH, sWh + boff);
                    ldsm4(bL, sWl + boff);
                    #pragma unroll
                    for (int s = 0; s < 2; s++) {
                        mma16816(acc[s][nt * 2],     aH[s], bH[0], bH[1]);
                        mma16816(acc[s][nt * 2 + 1], aH[s], bH[2], bH[3]);
                        mma16816(acc[s][nt * 2],     aH[s], bL[0], bL[1]);
                        mma16816(acc[s][nt * 2 + 1], aH[s], bL[2], bL[3]);
                        mma16816(acc[s][nt * 2],     aL[s], bH[0], bH[1]);
                        mma16816(acc[s][nt * 2 + 1], aL[s], bH[2], bH[3]);
                    }
                }
            }
        }
    }

    // ---- epilogue
    int ncol = (lane & 3) * 2;
    #pragma unroll
    for (int s = 0; s < 2; s++) {
        int row0 = m0 + wm * 32 + s * 16 + (lane >> 2);
        int row1 = row0 + 8;
        #pragma unroll
        for (int t8 = 0; t8 < 8; t8++) {
            int n = wn * 64 + t8 * 8 + ncol;
            float2 bv = *(const float2*)(bias + n);
            if (row0 < M) {
                float2 o = make_float2(acc[s][t8][0] + bv.x, acc[s][t8][1] + bv.y);
                *(float2*)(Cout + (size_t)row0 * DIMN + n) = o;
            }
            if (row1 < M) {
                float2 o = make_float2(acc[s][t8][2] + bv.x, acc[s][t8][3] + bv.y);
                *(float2*)(Cout + (size_t)row1 * DIMN + n) = o;
            }
        }
    }
}

__global__ void __launch_bounds__(256, 2)
k_gemm_user(float* __restrict__ out, int NU) {
    const __half* Ap[2] = {g_meanRh, g_xuh};
    const int wp[2] = {0, 1};
    gemm_core<2>(Ap, wp, out, g_biasU, NU, blockIdx.x * 128);
}

__global__ void __launch_bounds__(256, 2)
k_gemm_item(float* __restrict__ out, int NI) {
    const __half* Ap[3] = {g_meanBh, g_meanTh, g_xih};
    const int wp[3] = {2, 3, 4};
    gemm_core<3>(Ap, wp, out, g_biasI, NI, blockIdx.x * 128);
}

// ---------------- launch: two-stream pipelined graph ----------------
extern "C" void kernel_launch(void* const* d_in, const int* in_sizes, int n_in,
                              void* d_out, int out_size) {
    const float* xu  = (const float*)d_in[0];
    const float* xi  = (const float*)d_in[1];
    const float* xt  = (const float*)d_in[2];
    const int*   eb  = (const int*)d_in[3];
    const int*   er  = (const int*)d_in[4];
    const int*   et  = (const int*)d_in[5];
    const float* WlB = (const float*)d_in[6];
    const float* WrB = (const float*)d_in[7];
    const float* bB  = (const float*)d_in[8];
    const float* WlR = (const float*)d_in[9];
    const float* WrR = (const float*)d_in[10];
    const float* bR  = (const float*)d_in[11];
    const float* WlT = (const float*)d_in[12];
    const float* WrT = (const float*)d_in[13];
    const float* bT  = (const float*)d_in[14];

    int NU = in_sizes[0] / DIMN;
    int NI = in_sizes[1] / DIMN;
    int NT = in_sizes[2] / DIMN;
    int EB = in_sizes[3] / 2;
    int ER = in_sizes[4] / 2;
    int ET = in_sizes[5] / 2;

    float* out_user = (float*)d_out;
    float* out_item = (float*)d_out + (size_t)NU * DIMN;

    __half* dmB; cudaGetSymbolAddress((void**)&dmB, g_meanBh);
    __half* dmR; cudaGetSymbolAddress((void**)&dmR, g_meanRh);
    __half* dmT; cudaGetSymbolAddress((void**)&dmT, g_meanTh);
    __half* xuh; cudaGetSymbolAddress((void**)&xuh, g_xuh);
    __half* xih; cudaGetSymbolAddress((void**)&xih, g_xih);
    __half* xth; cudaGetSymbolAddress((void**)&xth, g_xth);

    const int SMEM_BYTES = 4 * 128 * TSTRIDE * 2;   // 73728
    cudaFuncSetAttribute(k_gemm_user, cudaFuncAttributeMaxDynamicSharedMemorySize, SMEM_BYTES);
    cudaFuncSetAttribute(k_gemm_item, cudaFuncAttributeMaxDynamicSharedMemorySize, SMEM_BYTES);

    int nblkU = (NU + 1023) / 1024;
    int nblkI = (NI + 1023) / 1024;

    cudaStream_t s0 = 0;  // capture-origin (legacy) stream

    // init: zero counters + weight prep, then fork
    k_init<<<(3 * (NU_MAX + 1) + 255) / 256, 256, 0, s0>>>(WlR, WrR, WlB, WlT,
                                                           WrB, WrT, bR, bB, bT);
    cudaEventRecord(g_sk.ev0, s0);
    cudaStreamWaitEvent(g_sk.sA, g_sk.ev0, 0);
    cudaStreamWaitEvent(g_sk.sB, g_sk.ev0, 0);

    // ---- conversions first on both streams; record BOTH events before any wait
    {
        int n = NI * DIMN;
        k_tohalf<<<(n / 4 + 255) / 256, 256, 0, g_sk.sA>>>(xi, xih, n);
    }
    cudaEventRecord(g_sk.evCA, g_sk.sA);   // xih ready
    {
        int n0 = NU * DIMN;
        int n1 = NT * DIMN;
        k_tohalf2<<<((n0 + n1) / 4 + 255) / 256, 256, 0, g_sk.sB>>>(xu, xuh, n0,
                                                                    xt, xth, n1);
    }
    cudaEventRecord(g_sk.evCB, g_sk.sB);   // xuh, xth ready

    // ---- stream A: rel 1 (rev) -> out_user
    k_hist1<<<(ER / 2 + 255) / 256, 256, 0, g_sk.sA>>>(er + ER, ER, 1);
    {
        dim3 g1(nblkU, 1);
        k_scan1p<<<g1, 1024, 0, g_sk.sA>>>(1, 1, NU);
        k_scan2<<<1, 1024, 0, g_sk.sA>>>(1, nblkU, NU, 1, nblkU, NU);
        dim3 g3((NU + 255) / 256, 1);
        k_scan3p<<<g3, 256, 0, g_sk.sA>>>(1, 1, NU);
    }
    k_fill1<<<(ER / 2 + 255) / 256, 256, 0, g_sk.sA>>>(er, ER, 1);
    k_agg1<<<(NU * 32 + 255) / 256, 256, 0, g_sk.sA>>>(xih, dmR, 1, NU);
    cudaStreamWaitEvent(g_sk.sA, g_sk.evCB, 0);   // need xuh for root panel
    k_gemm_user<<<(NU + 127) / 128, 256, SMEM_BYTES, g_sk.sA>>>(out_user, NU);
    cudaEventRecord(g_sk.evA, g_sk.sA);

    // ---- stream B: rels 0 (buys), 2 (tags) merged -> out_item
    k_hist2rel<<<((EB + ET) / 2 + 255) / 256, 256, 0, g_sk.sB>>>(eb + EB, et + ET,
                                                                 EB, ET);
    {
        dim3 g1(nblkI, 2);
        k_scan1p<<<g1, 1024, 0, g_sk.sB>>>(0, 2, NI);
        k_scan2<<<2, 1024, 0, g_sk.sB>>>(0, nblkI, NI, 2, nblkI, NI);
        dim3 g3((NI + 255) / 256, 2);
        k_scan3p<<<g3, 256, 0, g_sk.sB>>>(0, 2, NI);
    }
    k_fill2rel<<<((EB + ET) / 2 + 255) / 256, 256, 0, g_sk.sB>>>(eb, et, EB, ET);
    k_agg2rel<<<(2 * NI * 32 + 255) / 256, 256, 0, g_sk.sB>>>(xuh, dmB, xth, dmT, NI);
    cudaStreamWaitEvent(g_sk.sB, g_sk.evCA, 0);   // need xih for root panel
    k_gemm_item<<<(NI + 127) / 128, 256, SMEM_BYTES, g_sk.sB>>>(out_item, NI);
    cudaEventRecord(g_sk.evB, g_sk.sB);

    // ---- join back to origin stream
    cudaStreamWaitEvent(s0, g_sk.evA, 0);
    cudaStreamWaitEvent(s0, g_sk.evB, 0);
}